// round 8
// baseline (speedup 1.0000x reference)
#include <cuda_runtime.h>
#include <cuda_bf16.h>
#include <cstdint>

// ---------------- problem constants ----------------
#define NN   50000
#define MM   200000
#define EE   10000
#define DN_  256
#define DHA_ 64
#define DH_  256
#define DIN_ 320

#define MT   128          // rows per block
#define KC   64           // K chunk (one SW128 tile)
#define TILE_B (MT * 128) // bytes of one [128][64] bf16 tile = 16384

#define GRID1 ((MM + MT - 1) / MT)   // 1563

typedef unsigned long long u64;

// ---------------- device scratch ----------------
__device__ float g_agg[(size_t)EE * DH_];
__device__ float g_acc[(size_t)NN * DN_];
__device__ float g_deg[NN];

// transposed bf16 hi/lo weights: [N][K]
__device__ __nv_bfloat16 g_wa_hi[DN_ * DH_], g_wa_lo[DN_ * DH_];   // n2e_w1^T [256][256]
__device__ __nv_bfloat16 g_wb_hi[DH_ * DH_], g_wb_lo[DH_ * DH_];   // n2e_w2^T [256][256]
__device__ __nv_bfloat16 g_wc_hi[DH_ * DIN_], g_wc_lo[DH_ * DIN_]; // e2n_w1^T [256][320]
__device__ __nv_bfloat16 g_wd_hi[DN_ * DH_], g_wd_lo[DN_ * DH_];   // e2n_w2^T [256][256]

// ---------------- helpers ----------------
__device__ __forceinline__ uint32_t s2u(const void* p) {
    uint32_t a;
    asm("{ .reg .u64 t; cvta.to.shared.u64 t, %1; cvt.u32.u64 %0, t; }" : "=r"(a) : "l"(p));
    return a;
}
#define SW128(x) ((x) ^ ((((x) >> 3) & 0x70)))

__device__ __forceinline__ void ldsm4(uint32_t* r, uint32_t a) {
    asm volatile("ldmatrix.sync.aligned.m8n8.x4.shared.b16 {%0,%1,%2,%3}, [%4];"
        : "=r"(r[0]), "=r"(r[1]), "=r"(r[2]), "=r"(r[3]) : "r"(a));
}
__device__ __forceinline__ void mma16816(float* d, const uint32_t* a, const uint32_t* b) {
    asm volatile("mma.sync.aligned.m16n8k16.row.col.f32.bf16.bf16.f32 "
        "{%0,%1,%2,%3}, {%4,%5,%6,%7}, {%8,%9}, {%0,%1,%2,%3};"
        : "+f"(d[0]), "+f"(d[1]), "+f"(d[2]), "+f"(d[3])
        : "r"(a[0]), "r"(a[1]), "r"(a[2]), "r"(a[3]), "r"(b[0]), "r"(b[1]));
}
__device__ __forceinline__ void red2(float* p, float a, float b) {
    asm volatile("red.global.add.v2.f32 [%0], {%1, %2};" :: "l"(p), "f"(a), "f"(b) : "memory");
}
__device__ __forceinline__ void cpa16(uint32_t dst, const void* src) {
    asm volatile("cp.async.cg.shared.global [%0], [%1], 16;" :: "r"(dst), "l"(src) : "memory");
}
#define CP_COMMIT() asm volatile("cp.async.commit_group;" ::: "memory")
#define CP_WAIT1()  asm volatile("cp.async.wait_group 1;" ::: "memory")

// pack 2 floats -> bf16x2 (first arg -> low half / lower address)
__device__ __forceinline__ uint32_t pkbf(float lo, float hi) {
    uint32_t r;
    asm("cvt.rn.bf16x2.f32 %0, %1, %2;" : "=r"(r) : "f"(hi), "f"(lo));
    return r;
}
// convert float4 -> hi u64 (4 bf16) and lo u64 (residual)
__device__ __forceinline__ void cvt4(float4 v, u64& hi, u64& lo) {
    float hx = __bfloat162float(__float2bfloat16(v.x));
    float hy = __bfloat162float(__float2bfloat16(v.y));
    float hz = __bfloat162float(__float2bfloat16(v.z));
    float hw = __bfloat162float(__float2bfloat16(v.w));
    uint32_t h01 = pkbf(hx, hy), h23 = pkbf(hz, hw);
    uint32_t l01 = pkbf(v.x - hx, v.y - hy), l23 = pkbf(v.z - hz, v.w - hw);
    hi = (u64)h01 | ((u64)h23 << 32);
    lo = (u64)l01 | ((u64)l23 << 32);
}

// ---------------- cp.async stage load: one k32 half of B [256 n][32 k] hi+lo ----------------
// Stage s writes 16B units (s&1)*4 .. +3 of each 128B row (SW128 permutes units in-row),
// so the single [256][64] tile is a natural 2-stage ring.
__device__ __forceinline__ void load_B_half(const __nv_bfloat16* __restrict__ wh,
                                            const __nv_bfloat16* __restrict__ wl,
                                            int s, uint32_t bH, uint32_t bL,
                                            int tid, int kstride)
{
    const int kbase = s * 32;
    const int ubase = (s & 1) * 4;
    const __nv_bfloat16* sh = wh + (size_t)tid * kstride + kbase;
    const __nv_bfloat16* sl = wl + (size_t)tid * kstride + kbase;
    #pragma unroll
    for (int q = 0; q < 4; q++) {
        uint32_t off = SW128((uint32_t)(tid * 128 + (ubase + q) * 16));
        cpa16(bH + off, sh + q * 8);
        cpa16(bL + off, sl + q * 8);
    }
}

// ---------------- MMA for one k32 half (3 split terms) ----------------
__device__ __forceinline__ void gemm_half(uint32_t aH, uint32_t aL,
                                          uint32_t bH, uint32_t bL, int ks0,
                                          float (*acc)[8][4],
                                          int lane, int m_base, int n_base)
{
    const uint32_t swz  = (uint32_t)(lane & 7) << 4;
    const uint32_t arow = (uint32_t)(m_base + (lane & 15)) * 128;
    const uint32_t aka  = (uint32_t)((lane >> 4) << 3) * 2;
    const uint32_t brow = (uint32_t)(n_base + ((lane >> 4) << 3) + (lane & 7)) * 128;
    const uint32_t bka  = (uint32_t)(((lane >> 3) & 1) << 3) * 2;

    #pragma unroll
    for (int kk = 0; kk < 2; kk++) {
        const uint32_t koff = (uint32_t)(ks0 + kk) * 32;
        const uint32_t aoff = arow + ((koff + aka) ^ swz);
        const uint32_t boff = brow + ((koff + bka) ^ swz);
        uint32_t fa[4][4], fb[4][4], f2[4][4];
        #pragma unroll
        for (int mi = 0; mi < 4; mi++) ldsm4(fa[mi], aH + aoff + mi * 2048);
        #pragma unroll
        for (int j = 0; j < 4; j++)  ldsm4(fb[j], bH + boff + j * 2048);
        #pragma unroll
        for (int mi = 0; mi < 4; mi++)
            #pragma unroll
            for (int j = 0; j < 4; j++) {
                mma16816(acc[mi][2 * j],     fa[mi], fb[j]);
                mma16816(acc[mi][2 * j + 1], fa[mi], fb[j] + 2);
            }
        #pragma unroll
        for (int mi = 0; mi < 4; mi++) ldsm4(f2[mi], aL + aoff + mi * 2048);
        #pragma unroll
        for (int mi = 0; mi < 4; mi++)
            #pragma unroll
            for (int j = 0; j < 4; j++) {
                mma16816(acc[mi][2 * j],     f2[mi], fb[j]);
                mma16816(acc[mi][2 * j + 1], f2[mi], fb[j] + 2);
            }
        #pragma unroll
        for (int j = 0; j < 4; j++)  ldsm4(fb[j], bL + boff + j * 2048);
        #pragma unroll
        for (int mi = 0; mi < 4; mi++)
            #pragma unroll
            for (int j = 0; j < 4; j++) {
                mma16816(acc[mi][2 * j],     fa[mi], fb[j]);
                mma16816(acc[mi][2 * j + 1], fa[mi], fb[j] + 2);
            }
    }
}

// pipelined GEMM over S k32-halves (prologue loads for s=0,1 must already be committed)
template<int S>
__device__ __forceinline__ void run_gemm(const __nv_bfloat16* __restrict__ wh,
                                         const __nv_bfloat16* __restrict__ wl, int kstride,
                                         uint32_t aH, uint32_t aL, uint32_t bH, uint32_t bL,
                                         float (*acc)[8][4],
                                         int tid, int lane, int m_base, int n_base)
{
    #pragma unroll 1
    for (int s = 0; s < S; s++) {
        CP_WAIT1();
        __syncthreads();
        gemm_half(aH + (s >> 1) * TILE_B, aL + (s >> 1) * TILE_B,
                  bH, bL, (s & 1) * 2, acc, lane, m_base, n_base);
        __syncthreads();
        if (s + 2 < S) load_B_half(wh, wl, s + 2, bH, bL, tid, kstride);
        CP_COMMIT();
    }
}

__device__ __forceinline__ void init_bias_reg(float (*acc)[8][4],
                                              const float* __restrict__ b,
                                              int lane, int n_base)
{
    #pragma unroll
    for (int ni = 0; ni < 8; ni++) {
        int c = n_base + ni * 8 + 2 * (lane & 3);
        float v0 = __ldg(&b[c]), v1 = __ldg(&b[c + 1]);
        #pragma unroll
        for (int mi = 0; mi < 4; mi++) {
            acc[mi][ni][0] = v0; acc[mi][ni][1] = v1;
            acc[mi][ni][2] = v0; acc[mi][ni][3] = v1;
        }
    }
}

// LayerNorm + ReLU on register accumulators -> bf16 hi/lo into A2 smem tiles.
__device__ __forceinline__ void ln_apply(float (*acc)[8][4],
                                         const float* __restrict__ lng,
                                         const float* __restrict__ lnb,
                                         char* a2H, char* a2L, float* ps,
                                         int lane, int m_base, int n_base, int warp_n)
{
    #pragma unroll
    for (int mi = 0; mi < 4; mi++) {
        float sl = 0.f, ql = 0.f, sh = 0.f, qh = 0.f;
        #pragma unroll
        for (int ni = 0; ni < 8; ni++) {
            float a0 = acc[mi][ni][0], a1 = acc[mi][ni][1];
            float a2 = acc[mi][ni][2], a3 = acc[mi][ni][3];
            sl += a0 + a1; ql += a0 * a0 + a1 * a1;
            sh += a2 + a3; qh += a2 * a2 + a3 * a3;
        }
        sl += __shfl_xor_sync(0xffffffffu, sl, 1); sl += __shfl_xor_sync(0xffffffffu, sl, 2);
        ql += __shfl_xor_sync(0xffffffffu, ql, 1); ql += __shfl_xor_sync(0xffffffffu, ql, 2);
        sh += __shfl_xor_sync(0xffffffffu, sh, 1); sh += __shfl_xor_sync(0xffffffffu, sh, 2);
        qh += __shfl_xor_sync(0xffffffffu, qh, 1); qh += __shfl_xor_sync(0xffffffffu, qh, 2);
        if ((lane & 3) == 0) {
            int rl = m_base + mi * 16 + (lane >> 2);
            ps[rl * 4 + warp_n] = sl;        ps[512 + rl * 4 + warp_n] = ql;
            ps[(rl + 8) * 4 + warp_n] = sh;  ps[512 + (rl + 8) * 4 + warp_n] = qh;
        }
    }
    __syncthreads();
    float mu[4][2], rsd[4][2];
    #pragma unroll
    for (int mi = 0; mi < 4; mi++) {
        int rl = m_base + mi * 16 + (lane >> 2);
        #pragma unroll
        for (int h = 0; h < 2; h++) {
            int r = rl + h * 8;
            float s = ps[r * 4] + ps[r * 4 + 1] + ps[r * 4 + 2] + ps[r * 4 + 3];
            float q = ps[512 + r * 4] + ps[512 + r * 4 + 1] + ps[512 + r * 4 + 2] + ps[512 + r * 4 + 3];
            float m = s * (1.f / 256.f);
            float var = q * (1.f / 256.f) - m * m;
            mu[mi][h] = m;
            rsd[mi][h] = rsqrtf(var + 1e-5f);
        }
    }
    __syncthreads();
    #pragma unroll
    for (int mi = 0; mi < 4; mi++) {
        int rl = m_base + mi * 16 + (lane >> 2);
        int rh = rl + 8;
        uint32_t rswz = (uint32_t)(lane >> 2) << 4;
        #pragma unroll
        for (int ni = 0; ni < 8; ni++) {
            int cl = ni * 8 + 2 * (lane & 3);
            int c  = n_base + cl;
            float g0 = __ldg(&lng[c]),  g1 = __ldg(&lng[c + 1]);
            float B0 = __ldg(&lnb[c]),  B1 = __ldg(&lnb[c + 1]);
            uint32_t kb = ((uint32_t)(cl * 2)) ^ rswz;
            {
                float t0 = fmaxf((acc[mi][ni][0] - mu[mi][0]) * rsd[mi][0] * g0 + B0, 0.f);
                float t1 = fmaxf((acc[mi][ni][1] - mu[mi][0]) * rsd[mi][0] * g1 + B1, 0.f);
                float h0 = __bfloat162float(__float2bfloat16(t0));
                float h1 = __bfloat162float(__float2bfloat16(t1));
                uint32_t off = (uint32_t)warp_n * TILE_B + (uint32_t)rl * 128 + kb;
                *(uint32_t*)(a2H + off) = pkbf(h0, h1);
                *(uint32_t*)(a2L + off) = pkbf(t0 - h0, t1 - h1);
            }
            {
                float t0 = fmaxf((acc[mi][ni][2] - mu[mi][1]) * rsd[mi][1] * g0 + B0, 0.f);
                float t1 = fmaxf((acc[mi][ni][3] - mu[mi][1]) * rsd[mi][1] * g1 + B1, 0.f);
                float h0 = __bfloat162float(__float2bfloat16(t0));
                float h1 = __bfloat162float(__float2bfloat16(t1));
                uint32_t off = (uint32_t)warp_n * TILE_B + (uint32_t)rh * 128 + kb;
                *(uint32_t*)(a2H + off) = pkbf(h0, h1);
                *(uint32_t*)(a2L + off) = pkbf(t0 - h0, t1 - h1);
            }
        }
    }
}

// ---------------- prep: all 4 weights -> transposed bf16 hi/lo [N][K], one kernel ----------------
#define PREP_TOTAL (65536 + 65536 + 81920 + 65536)
__global__ void k_prep_all(const float* __restrict__ wa, const float* __restrict__ wb,
                           const float* __restrict__ wc, const float* __restrict__ wd)
{
    int i = blockIdx.x * 256 + threadIdx.x;
    if (i >= PREP_TOTAL) return;
    const float* w; __nv_bfloat16 *th, *tl; int K, N, j;
    if (i < 65536)       { w = wa; th = g_wa_hi; tl = g_wa_lo; K = 256; N = 256; j = i; }
    else if (i < 131072) { w = wb; th = g_wb_hi; tl = g_wb_lo; K = 256; N = 256; j = i - 65536; }
    else if (i < 212992) { w = wc; th = g_wc_hi; tl = g_wc_lo; K = 320; N = 256; j = i - 131072; }
    else                 { w = wd; th = g_wd_hi; tl = g_wd_lo; K = 256; N = 256; j = i - 212992; }
    int n = j / K, k = j - n * K;
    float v = __ldg(&w[(size_t)k * N + n]);
    __nv_bfloat16 h = __float2bfloat16(v);
    th[j] = h;
    tl[j] = __float2bfloat16(v - __bfloat162float(h));
}

// ---------------- smem offsets ----------------
#define K1_AHI 0
#define K1_ALO 65536
#define K1_BHI 131072
#define K1_BLO 163840
#define K1_PS  196608
#define K1_EID 200704
#define K1_NID 201216
#define K1_SMEM 201728

#define K2_AHI 0
#define K2_ALO 81920
#define K2_BHI 163840
#define K2_BLO 196608
#define K2_EID 229376
#define K2_NID 229888
#define K2_RC  230400
#define K2_SMEM 230944
#define K2_PS  (K2_AHI + 4 * TILE_B)   // dead A_hi tile 4 after GEMM1

// =====================================================================
// Kernel 1: node -> hyperedge
// =====================================================================
__global__ __launch_bounds__(256, 1)
void k_n2e(const float* __restrict__ x,
           const int*   __restrict__ node_ids,
           const int*   __restrict__ he_ids,
           const float* __restrict__ b1,
           const float* __restrict__ lng, const float* __restrict__ lnb,
           const float* __restrict__ b2)
{
    extern __shared__ char sm[];
    const uint32_t smb = s2u(sm);
    const int tid = threadIdx.x, wid = tid >> 5, lane = tid & 31;
    const int warp_m = wid >> 2, warp_n = wid & 3;
    const int m_base = warp_m * 64, n_base = warp_n * 64;
    const int m0 = blockIdx.x * MT;

    int* eid_s = (int*)(sm + K1_EID);
    int* nid_s = (int*)(sm + K1_NID);
    float* ps  = (float*)(sm + K1_PS);
    const uint32_t bH = smb + K1_BHI, bL = smb + K1_BLO;

    // GEMM1 B prologue before anything else (overlaps the A gather)
    load_B_half(g_wa_hi, g_wa_lo, 0, bH, bL, tid, DN_); CP_COMMIT();
    load_B_half(g_wa_hi, g_wa_lo, 1, bH, bL, tid, DN_); CP_COMMIT();

    if (tid < MT) {
        int m = m0 + tid;
        int mc = m < MM ? m : MM - 1;
        eid_s[tid] = he_ids[mc];
        nid_s[tid] = node_ids[mc];
    }
    __syncthreads();

    // gather x -> bf16 hi/lo swizzled A tiles
    for (int i = tid; i < MT * 64; i += 256) {
        int r = i >> 6, c4 = i & 63;
        float4 v = __ldg((const float4*)&x[(size_t)nid_s[r] * DN_ + c4 * 4]);
        u64 hi, lo; cvt4(v, hi, lo);
        int k = c4 * 4, tile = k >> 6, kin = k & 63;
        uint32_t off = tile * TILE_B + SW128((uint32_t)(r * 128 + kin * 2));
        *(u64*)(sm + K1_AHI + off) = hi;
        *(u64*)(sm + K1_ALO + off) = lo;
    }

    float acc[4][8][4];
    init_bias_reg(acc, b1, lane, n_base);

    // ---- GEMM1: D = X @ W1 (8 k32 halves, pipelined) ----
    run_gemm<8>(g_wa_hi, g_wa_lo, DN_, smb + K1_AHI, smb + K1_ALO, bH, bL,
                acc, tid, lane, m_base, n_base);

    // prefetch GEMM2's first two B halves during the LayerNorm
    load_B_half(g_wb_hi, g_wb_lo, 0, bH, bL, tid, DH_); CP_COMMIT();
    load_B_half(g_wb_hi, g_wb_lo, 1, bH, bL, tid, DH_); CP_COMMIT();

    // ---- LN + ReLU -> A2 tiles (alias A1) ----
    ln_apply(acc, lng, lnb, sm + K1_AHI, sm + K1_ALO, ps, lane, m_base, n_base, warp_n);
    init_bias_reg(acc, b2, lane, n_base);

    // ---- GEMM2: D = H @ W2 ----
    run_gemm<8>(g_wb_hi, g_wb_lo, DH_, smb + K1_AHI, smb + K1_ALO, bH, bL,
                acc, tid, lane, m_base, n_base);

    // ---- epilogue: scatter-add to g_agg ----
    #pragma unroll
    for (int mi = 0; mi < 4; mi++) {
        int rl = m_base + mi * 16 + (lane >> 2);
        int rh = rl + 8;
        if (m0 + rl < MM) {
            int e = eid_s[rl];
            #pragma unroll
            for (int ni = 0; ni < 8; ni++) {
                int c = n_base + ni * 8 + 2 * (lane & 3);
                red2(&g_agg[(size_t)e * DH_ + c], acc[mi][ni][0], acc[mi][ni][1]);
            }
        }
        if (m0 + rh < MM) {
            int e = eid_s[rh];
            #pragma unroll
            for (int ni = 0; ni < 8; ni++) {
                int c = n_base + ni * 8 + 2 * (lane & 3);
                red2(&g_agg[(size_t)e * DH_ + c], acc[mi][ni][2], acc[mi][ni][3]);
            }
        }
    }
}

// =====================================================================
// Kernel 2: hyperedge -> node, GEMM1 K = 320
// =====================================================================
__global__ __launch_bounds__(256, 1)
void k_e2n(const int*   __restrict__ node_ids,
           const int*   __restrict__ he_ids,
           const float* __restrict__ he_attr,
           const float* __restrict__ he_count,
           const float* __restrict__ b1,
           const float* __restrict__ lng, const float* __restrict__ lnb,
           const float* __restrict__ b2)
{
    extern __shared__ char sm[];
    const uint32_t smb = s2u(sm);
    const int tid = threadIdx.x, wid = tid >> 5, lane = tid & 31;
    const int warp_m = wid >> 2, warp_n = wid & 3;
    const int m_base = warp_m * 64, n_base = warp_n * 64;
    const int m0 = blockIdx.x * MT;

    int* eid_s = (int*)(sm + K2_EID);
    int* nid_s = (int*)(sm + K2_NID);
    float* rc_s = (float*)(sm + K2_RC);
    float* ps  = (float*)(sm + K2_PS);
    const uint32_t bH = smb + K2_BHI, bL = smb + K2_BLO;

    load_B_half(g_wc_hi, g_wc_lo, 0, bH, bL, tid, DIN_); CP_COMMIT();
    load_B_half(g_wc_hi, g_wc_lo, 1, bH, bL, tid, DIN_); CP_COMMIT();

    if (tid < MT) {
        int m = m0 + tid;
        int mc = m < MM ? m : MM - 1;
        int e = he_ids[mc];
        eid_s[tid] = e;
        nid_s[tid] = node_ids[mc];
        rc_s[tid]  = 1.f / (__ldg(&he_count[e]) + 1e-6f);
    }
    __syncthreads();

    // gather [he_attr | agg/cnt] -> bf16 hi/lo swizzled A tiles (5 tiles)
    for (int i = tid; i < MT * 16; i += 256) {            // attr: k 0..63 (tile 0)
        int r = i >> 4, q = i & 15;
        float4 v = __ldg((const float4*)&he_attr[(size_t)eid_s[r] * DHA_ + q * 4]);
        u64 hi, lo; cvt4(v, hi, lo);
        uint32_t off = SW128((uint32_t)(r * 128 + q * 8));
        *(u64*)(sm + K2_AHI + off) = hi;
        *(u64*)(sm + K2_ALO + off) = lo;
    }
    for (int i = tid; i < MT * 64; i += 256) {            // agg: k 64..319 (tiles 1-4)
        int r = i >> 6, c4 = i & 63;
        float rc = rc_s[r];
        float4 v = *(const float4*)&g_agg[(size_t)eid_s[r] * DH_ + c4 * 4];
        v.x *= rc; v.y *= rc; v.z *= rc; v.w *= rc;
        u64 hi, lo; cvt4(v, hi, lo);
        int k = 64 + c4 * 4, tile = k >> 6, kin = k & 63;
        uint32_t off = tile * TILE_B + SW128((uint32_t)(r * 128 + kin * 2));
        *(u64*)(sm + K2_AHI + off) = hi;
        *(u64*)(sm + K2_ALO + off) = lo;
    }

    float acc[4][8][4];
    init_bias_reg(acc, b1, lane, n_base);

    // ---- GEMM1: D = [attr|agg] @ W1, K = 320 (10 halves) ----
    run_gemm<10>(g_wc_hi, g_wc_lo, DIN_, smb + K2_AHI, smb + K2_ALO, bH, bL,
                 acc, tid, lane, m_base, n_base);

    load_B_half(g_wd_hi, g_wd_lo, 0, bH, bL, tid, DH_); CP_COMMIT();
    load_B_half(g_wd_hi, g_wd_lo, 1, bH, bL, tid, DH_); CP_COMMIT();

    // ---- LN + ReLU -> A2 tiles (alias A1 tiles 0-3; ps in dead tile 4) ----
    ln_apply(acc, lng, lnb, sm + K2_AHI, sm + K2_ALO, ps, lane, m_base, n_base, warp_n);
    init_bias_reg(acc, b2, lane, n_base);

    // ---- GEMM2: D = G @ W2, K = 256 ----
    run_gemm<8>(g_wd_hi, g_wd_lo, DH_, smb + K2_AHI, smb + K2_ALO, bH, bL,
                acc, tid, lane, m_base, n_base);

    // ---- epilogue: relu(D) scatter-add to g_acc + degree ----
    #pragma unroll
    for (int mi = 0; mi < 4; mi++) {
        int rl = m_base + mi * 16 + (lane >> 2);
        int rh = rl + 8;
        if (m0 + rl < MM) {
            int n = nid_s[rl];
            #pragma unroll
            for (int ni = 0; ni < 8; ni++) {
                int c = n_base + ni * 8 + 2 * (lane & 3);
                red2(&g_acc[(size_t)n * DN_ + c],
                     fmaxf(acc[mi][ni][0], 0.f), fmaxf(acc[mi][ni][1], 0.f));
            }
            if (warp_n == 0 && (lane & 3) == 0)
                asm volatile("red.global.add.f32 [%0], %1;" :: "l"(&g_deg[n]), "f"(1.f) : "memory");
        }
        if (m0 + rh < MM) {
            int n = nid_s[rh];
            #pragma unroll
            for (int ni = 0; ni < 8; ni++) {
                int c = n_base + ni * 8 + 2 * (lane & 3);
                red2(&g_acc[(size_t)n * DN_ + c],
                     fmaxf(acc[mi][ni][2], 0.f), fmaxf(acc[mi][ni][3], 0.f));
            }
            if (warp_n == 0 && (lane & 3) == 0)
                asm volatile("red.global.add.f32 [%0], %1;" :: "l"(&g_deg[n]), "f"(1.f) : "memory");
        }
    }
}

// =====================================================================
// Kernel 3: out = x + LN(g_acc / (deg + eps)).  Warp per node row.
// =====================================================================
__global__ __launch_bounds__(256, 4)
void k_final(const float* __restrict__ x,
             const float* __restrict__ lng, const float* __restrict__ lnb,
             float* __restrict__ out)
{
    const int lane = threadIdx.x & 31;
    const int n = blockIdx.x * 8 + (threadIdx.x >> 5);
    if (n >= NN) return;

    float rd = 1.f / (g_deg[n] + 1e-6f);
    float v[8], s = 0.f, sq = 0.f;
    #pragma unroll
    for (int j = 0; j < 8; j++) {
        v[j] = g_acc[(size_t)n * DN_ + lane + j * 32] * rd;
        s += v[j]; sq += v[j] * v[j];
    }
    #pragma unroll
    for (int o = 16; o; o >>= 1) {
        s  += __shfl_xor_sync(0xffffffffu, s, o);
        sq += __shfl_xor_sync(0xffffffffu, sq, o);
    }
    float mu = s * (1.f / DN_);
    float var = sq * (1.f / DN_) - mu * mu;
    float rs = rsqrtf(var + 1e-5f);
    #pragma unroll
    for (int j = 0; j < 8; j++) {
        int c = lane + j * 32;
        float t = (v[j] - mu) * rs * __ldg(&lng[c]) + __ldg(&lnb[c]);
        out[(size_t)n * DN_ + c] = __ldg(&x[(size_t)n * DN_ + c]) + t;
    }
}

// =====================================================================
// launcher
// =====================================================================
extern "C" void kernel_launch(void* const* d_in, const int* in_sizes, int n_in,
                              void* d_out, int out_size)
{
    const float* x        = (const float*)d_in[0];
    const int*   node_ids = (const int*)  d_in[1];
    const int*   he_ids   = (const int*)  d_in[2];
    const float* he_attr  = (const float*)d_in[3];
    const float* he_count = (const float*)d_in[4];
    const float* n2e_w1   = (const float*)d_in[5];
    const float* n2e_b1   = (const float*)d_in[6];
    const float* n2e_lng  = (const float*)d_in[7];
    const float* n2e_lnb  = (const float*)d_in[8];
    const float* n2e_w2   = (const float*)d_in[9];
    const float* n2e_b2   = (const float*)d_in[10];
    const float* e2n_w1   = (const float*)d_in[11];
    const float* e2n_b1   = (const float*)d_in[12];
    const float* e2n_lng  = (const float*)d_in[13];
    const float* e2n_lnb  = (const float*)d_in[14];
    const float* e2n_w2   = (const float*)d_in[15];
    const float* e2n_b2   = (const float*)d_in[16];
    const float* ln_g     = (const float*)d_in[17];
    const float* ln_b     = (const float*)d_in[18];
    float* out = (float*)d_out;

    void *p_agg, *p_acc, *p_deg;
    cudaGetSymbolAddress(&p_agg, g_agg);
    cudaGetSymbolAddress(&p_acc, g_acc);
    cudaGetSymbolAddress(&p_deg, g_deg);
    cudaMemsetAsync(p_agg, 0, sizeof(float) * (size_t)EE * DH_);
    cudaMemsetAsync(p_acc, 0, sizeof(float) * (size_t)NN * DN_);
    cudaMemsetAsync(p_deg, 0, sizeof(float) * NN);

    k_prep_all<<<(PREP_TOTAL + 255) / 256, 256>>>(n2e_w1, n2e_w2, e2n_w1, e2n_w2);

    cudaFuncSetAttribute(k_n2e, cudaFuncAttributeMaxDynamicSharedMemorySize, K1_SMEM);
    cudaFuncSetAttribute(k_e2n, cudaFuncAttributeMaxDynamicSharedMemorySize, K2_SMEM);

    k_n2e<<<GRID1, 256, K1_SMEM>>>(x, node_ids, he_ids,
                                   n2e_b1, n2e_lng, n2e_lnb, n2e_b2);
    k_e2n<<<GRID1, 256, K2_SMEM>>>(node_ids, he_ids, he_attr, he_count,
                                   e2n_b1, e2n_lng, e2n_lnb, e2n_b2);
    k_final<<<(NN + 7) / 8, 256>>>(x, ln_g, ln_b, out);
}

// round 10
// speedup vs baseline: 1.6824x; 1.6824x over previous
#include <cuda_runtime.h>
#include <cuda_fp16.h>
#include <cstdint>

// ---------------- problem constants ----------------
#define NN   50000
#define MM   200000
#define EE   10000
#define DN_  256
#define DHA_ 64
#define DH_  256
#define DIN_ 320

#define MT   128          // rows per block
#define KC   64           // K chunk (one SW128 tile)
#define TILE_B (MT * 128) // bytes of one [128][64] fp16 tile = 16384
#define BCH  32768        // bytes of one B chunk buffer [256][64] fp16

#define GRID1 ((MM + MT - 1) / MT)   // 1563

typedef unsigned long long u64;

// ---------------- device scratch ----------------
__device__ float g_agg[(size_t)EE * DH_];
__device__ float g_acc[(size_t)NN * DN_];
__device__ float g_deg[NN];

// transposed fp16 hi/lo weights: [N][K]
__device__ __half g_wa_hi[DN_ * DH_], g_wa_lo[DN_ * DH_];   // n2e_w1^T [256][256]
__device__ __half g_wb_hi[DH_ * DH_], g_wb_lo[DH_ * DH_];   // n2e_w2^T [256][256]
__device__ __half g_wc_hi[DH_ * DIN_], g_wc_lo[DH_ * DIN_]; // e2n_w1^T [256][320]
__device__ __half g_wd_hi[DN_ * DH_], g_wd_lo[DN_ * DH_];   // e2n_w2^T [256][256]

// ---------------- helpers ----------------
__device__ __forceinline__ uint32_t s2u(const void* p) {
    uint32_t a;
    asm("{ .reg .u64 t; cvta.to.shared.u64 t, %1; cvt.u32.u64 %0, t; }" : "=r"(a) : "l"(p));
    return a;
}
#define SW128(x) ((x) ^ ((((x) >> 3) & 0x70)))

__device__ __forceinline__ void ldsm4(uint32_t* r, uint32_t a) {
    asm volatile("ldmatrix.sync.aligned.m8n8.x4.shared.b16 {%0,%1,%2,%3}, [%4];"
        : "=r"(r[0]), "=r"(r[1]), "=r"(r[2]), "=r"(r[3]) : "r"(a));
}
__device__ __forceinline__ void mma16816h(float* d, const uint32_t* a, const uint32_t* b) {
    asm volatile("mma.sync.aligned.m16n8k16.row.col.f32.f16.f16.f32 "
        "{%0,%1,%2,%3}, {%4,%5,%6,%7}, {%8,%9}, {%0,%1,%2,%3};"
        : "+f"(d[0]), "+f"(d[1]), "+f"(d[2]), "+f"(d[3])
        : "r"(a[0]), "r"(a[1]), "r"(a[2]), "r"(a[3]), "r"(b[0]), "r"(b[1]));
}
__device__ __forceinline__ void red2(float* p, float a, float b) {
    asm volatile("red.global.add.v2.f32 [%0], {%1, %2};" :: "l"(p), "f"(a), "f"(b) : "memory");
}
__device__ __forceinline__ void cpa16(uint32_t dst, const void* src) {
    asm volatile("cp.async.cg.shared.global [%0], [%1], 16;" :: "r"(dst), "l"(src) : "memory");
}
#define CP_COMMIT() asm volatile("cp.async.commit_group;" ::: "memory")
#define CP_WAIT1()  asm volatile("cp.async.wait_group 1;" ::: "memory")

// pack 2 floats -> fp16x2 (first arg -> low half / lower address)
__device__ __forceinline__ uint32_t pkh(float lo, float hi) {
    __half2 h = __floats2half2_rn(lo, hi);
    return *reinterpret_cast<uint32_t*>(&h);
}

// ---------------- B chunk load: [256 n][64 k] fp16 hi+lo, coalesced cp.async ----------------
__device__ __forceinline__ void load_B_chunk(const __half* __restrict__ wh,
                                             const __half* __restrict__ wl,
                                             int kc, int kstride,
                                             uint32_t bH, uint32_t bL, int tid)
{
    #pragma unroll
    for (int it = 0; it < 8; it++) {
        int i = it * 256 + tid;
        int n = i >> 3, q = i & 7;
        size_t src = (size_t)n * kstride + kc * KC + q * 8;
        uint32_t off = SW128((uint32_t)(n * 128 + q * 16));
        cpa16(bH + off, wh + src);
        cpa16(bL + off, wl + src);
    }
}

// ---------------- MMA for one k64 chunk (2 fp16 terms: aF*bH + aF*bL) ----------------
__device__ __forceinline__ void gemm_chunk(uint32_t aT, uint32_t bH, uint32_t bL,
                                           float (*acc)[8][4],
                                           int lane, int m_base, int n_base)
{
    const uint32_t swz  = (uint32_t)(lane & 7) << 4;
    const uint32_t arow = (uint32_t)(m_base + (lane & 15)) * 128;
    const uint32_t aka  = (uint32_t)((lane >> 4) << 3) * 2;
    const uint32_t brow = (uint32_t)(n_base + ((lane >> 4) << 3) + (lane & 7)) * 128;
    const uint32_t bka  = (uint32_t)(((lane >> 3) & 1) << 3) * 2;

    #pragma unroll
    for (int ks = 0; ks < 4; ks++) {
        const uint32_t koff = (uint32_t)ks * 32;
        const uint32_t aoff = arow + ((koff + aka) ^ swz);
        const uint32_t boff = brow + ((koff + bka) ^ swz);
        uint32_t fa[4][4], fb[4][4];
        #pragma unroll
        for (int mi = 0; mi < 4; mi++) ldsm4(fa[mi], aT + aoff + mi * 2048);
        #pragma unroll
        for (int j = 0; j < 4; j++)  ldsm4(fb[j], bH + boff + j * 2048);
        #pragma unroll
        for (int mi = 0; mi < 4; mi++)
            #pragma unroll
            for (int j = 0; j < 4; j++) {
                mma16816h(acc[mi][2 * j],     fa[mi], fb[j]);
                mma16816h(acc[mi][2 * j + 1], fa[mi], fb[j] + 2);
            }
        #pragma unroll
        for (int j = 0; j < 4; j++)  ldsm4(fb[j], bL + boff + j * 2048);
        #pragma unroll
        for (int mi = 0; mi < 4; mi++)
            #pragma unroll
            for (int j = 0; j < 4; j++) {
                mma16816h(acc[mi][2 * j],     fa[mi], fb[j]);
                mma16816h(acc[mi][2 * j + 1], fa[mi], fb[j] + 2);
            }
    }
}

// double-buffered GEMM over C k64 chunks.
// buf(c) = b0 + ((po + c) & 1) * 2*BCH ; bL = bH + BCH.
// Prologue: chunk 0 must already be issued+committed into buf(po).
template<int C>
__device__ __forceinline__ void run_gemm(const __half* __restrict__ wh,
                                         const __half* __restrict__ wl, int kstride,
                                         uint32_t aBase, uint32_t b0, int po,
                                         float (*acc)[8][4],
                                         int tid, int lane, int m_base, int n_base)
{
    #pragma unroll 1
    for (int c = 0; c < C; c++) {
        if (c + 1 < C) {
            uint32_t nb = b0 + (uint32_t)((po + c + 1) & 1) * (2 * BCH);
            load_B_chunk(wh, wl, c + 1, kstride, nb, nb + BCH, tid);
        }
        CP_COMMIT();
        CP_WAIT1();
        __syncthreads();
        uint32_t cb = b0 + (uint32_t)((po + c) & 1) * (2 * BCH);
        gemm_chunk(aBase + c * TILE_B, cb, cb + BCH, acc, lane, m_base, n_base);
        __syncthreads();
    }
}

__device__ __forceinline__ void init_bias_reg(float (*acc)[8][4],
                                              const float* __restrict__ b,
                                              int lane, int n_base)
{
    #pragma unroll
    for (int ni = 0; ni < 8; ni++) {
        int c = n_base + ni * 8 + 2 * (lane & 3);
        float v0 = __ldg(&b[c]), v1 = __ldg(&b[c + 1]);
        #pragma unroll
        for (int mi = 0; mi < 4; mi++) {
            acc[mi][ni][0] = v0; acc[mi][ni][1] = v1;
            acc[mi][ni][2] = v0; acc[mi][ni][3] = v1;
        }
    }
}

// LayerNorm + ReLU on register accumulators -> single fp16 A2 smem tiles.
__device__ __forceinline__ void ln_apply(float (*acc)[8][4],
                                         const float* __restrict__ lng,
                                         const float* __restrict__ lnb,
                                         char* a2, float* ps,
                                         int lane, int m_base, int n_base, int warp_n)
{
    #pragma unroll
    for (int mi = 0; mi < 4; mi++) {
        float sl = 0.f, ql = 0.f, sh = 0.f, qh = 0.f;
        #pragma unroll
        for (int ni = 0; ni < 8; ni++) {
            float a0 = acc[mi][ni][0], a1 = acc[mi][ni][1];
            float a2v = acc[mi][ni][2], a3 = acc[mi][ni][3];
            sl += a0 + a1; ql += a0 * a0 + a1 * a1;
            sh += a2v + a3; qh += a2v * a2v + a3 * a3;
        }
        sl += __shfl_xor_sync(0xffffffffu, sl, 1); sl += __shfl_xor_sync(0xffffffffu, sl, 2);
        ql += __shfl_xor_sync(0xffffffffu, ql, 1); ql += __shfl_xor_sync(0xffffffffu, ql, 2);
        sh += __shfl_xor_sync(0xffffffffu, sh, 1); sh += __shfl_xor_sync(0xffffffffu, sh, 2);
        qh += __shfl_xor_sync(0xffffffffu, qh, 1); qh += __shfl_xor_sync(0xffffffffu, qh, 2);
        if ((lane & 3) == 0) {
            int rl = m_base + mi * 16 + (lane >> 2);
            ps[rl * 4 + warp_n] = sl;        ps[512 + rl * 4 + warp_n] = ql;
            ps[(rl + 8) * 4 + warp_n] = sh;  ps[512 + (rl + 8) * 4 + warp_n] = qh;
        }
    }
    __syncthreads();
    float mu[4][2], rsd[4][2];
    #pragma unroll
    for (int mi = 0; mi < 4; mi++) {
        int rl = m_base + mi * 16 + (lane >> 2);
        #pragma unroll
        for (int h = 0; h < 2; h++) {
            int r = rl + h * 8;
            float s = ps[r * 4] + ps[r * 4 + 1] + ps[r * 4 + 2] + ps[r * 4 + 3];
            float q = ps[512 + r * 4] + ps[512 + r * 4 + 1] + ps[512 + r * 4 + 2] + ps[512 + r * 4 + 3];
            float m = s * (1.f / 256.f);
            float var = q * (1.f / 256.f) - m * m;
            mu[mi][h] = m;
            rsd[mi][h] = rsqrtf(var + 1e-5f);
        }
    }
    __syncthreads();
    #pragma unroll
    for (int mi = 0; mi < 4; mi++) {
        int rl = m_base + mi * 16 + (lane >> 2);
        int rh = rl + 8;
        uint32_t rswz = (uint32_t)(lane >> 2) << 4;
        #pragma unroll
        for (int ni = 0; ni < 8; ni++) {
            int cl = ni * 8 + 2 * (lane & 3);
            int c  = n_base + cl;
            float g0 = __ldg(&lng[c]),  g1 = __ldg(&lng[c + 1]);
            float B0 = __ldg(&lnb[c]),  B1 = __ldg(&lnb[c + 1]);
            uint32_t kb = ((uint32_t)(cl * 2)) ^ rswz;
            {
                float t0 = fmaxf((acc[mi][ni][0] - mu[mi][0]) * rsd[mi][0] * g0 + B0, 0.f);
                float t1 = fmaxf((acc[mi][ni][1] - mu[mi][0]) * rsd[mi][0] * g1 + B1, 0.f);
                *(uint32_t*)(a2 + (uint32_t)warp_n * TILE_B + (uint32_t)rl * 128 + kb) = pkh(t0, t1);
            }
            {
                float t0 = fmaxf((acc[mi][ni][2] - mu[mi][1]) * rsd[mi][1] * g0 + B0, 0.f);
                float t1 = fmaxf((acc[mi][ni][3] - mu[mi][1]) * rsd[mi][1] * g1 + B1, 0.f);
                *(uint32_t*)(a2 + (uint32_t)warp_n * TILE_B + (uint32_t)rh * 128 + kb) = pkh(t0, t1);
            }
        }
    }
}

// ---------------- prep: all 4 weights -> transposed fp16 hi/lo [N][K] ----------------
#define PREP_TOTAL (65536 + 65536 + 81920 + 65536)
__global__ void k_prep_all(const float* __restrict__ wa, const float* __restrict__ wb,
                           const float* __restrict__ wc, const float* __restrict__ wd)
{
    int i = blockIdx.x * 256 + threadIdx.x;
    if (i >= PREP_TOTAL) return;
    const float* w; __half *th, *tl; int K, N, j;
    if (i < 65536)       { w = wa; th = g_wa_hi; tl = g_wa_lo; K = 256; N = 256; j = i; }
    else if (i < 131072) { w = wb; th = g_wb_hi; tl = g_wb_lo; K = 256; N = 256; j = i - 65536; }
    else if (i < 212992) { w = wc; th = g_wc_hi; tl = g_wc_lo; K = 320; N = 256; j = i - 131072; }
    else                 { w = wd; th = g_wd_hi; tl = g_wd_lo; K = 256; N = 256; j = i - 212992; }
    int n = j / K, k = j - n * K;
    float v = __ldg(&w[(size_t)k * N + n]);
    __half h = __float2half(v);
    th[j] = h;
    tl[j] = __float2half(v - __half2float(h));
}

// ---------------- smem offsets ----------------
// K1: A 4 fp16 tiles (64K), B ring 4x32K (128K), ps 4K, ids
#define K1_A   0
#define K1_B0  65536
#define K1_PS  196608
#define K1_EID 200704
#define K1_NID 201216
#define K1_SMEM 201728

// K2: A 5 fp16 tiles (80K), B ring 4x32K (128K), ps 4K, ids
#define K2_A   0
#define K2_B0  81920
#define K2_PS  212992
#define K2_EID 217088
#define K2_NID 217600
#define K2_RC  218112
#define K2_SMEM 218656

// =====================================================================
// Kernel 1: node -> hyperedge
// =====================================================================
__global__ __launch_bounds__(256, 1)
void k_n2e(const float* __restrict__ x,
           const int*   __restrict__ node_ids,
           const int*   __restrict__ he_ids,
           const float* __restrict__ b1,
           const float* __restrict__ lng, const float* __restrict__ lnb,
           const float* __restrict__ b2)
{
    extern __shared__ char sm[];
    const uint32_t smb = s2u(sm);
    const int tid = threadIdx.x, wid = tid >> 5, lane = tid & 31;
    const int warp_m = wid >> 2, warp_n = wid & 3;
    const int m_base = warp_m * 64, n_base = warp_n * 64;
    const int m0 = blockIdx.x * MT;

    int* eid_s = (int*)(sm + K1_EID);
    int* nid_s = (int*)(sm + K1_NID);
    float* ps  = (float*)(sm + K1_PS);
    const uint32_t b0 = smb + K1_B0;

    // GEMM1 chunk-0 prologue (overlaps the A gather)
    load_B_chunk(g_wa_hi, g_wa_lo, 0, DN_, b0, b0 + BCH, tid);
    CP_COMMIT();

    if (tid < MT) {
        int m = m0 + tid;
        int mc = m < MM ? m : MM - 1;
        eid_s[tid] = he_ids[mc];
        nid_s[tid] = node_ids[mc];
    }
    __syncthreads();

    // gather x -> single fp16 swizzled A tiles
    for (int i = tid; i < MT * 64; i += 256) {
        int r = i >> 6, c4 = i & 63;
        float4 v = __ldg((const float4*)&x[(size_t)nid_s[r] * DN_ + c4 * 4]);
        u64 h = (u64)pkh(v.x, v.y) | ((u64)pkh(v.z, v.w) << 32);
        int k = c4 * 4, tile = k >> 6, kin = k & 63;
        *(u64*)(sm + K1_A + tile * TILE_B + SW128((uint32_t)(r * 128 + kin * 2))) = h;
    }

    float acc[4][8][4];
    init_bias_reg(acc, b1, lane, n_base);

    // ---- GEMM1: D = X @ W1 (4 chunks, po=0) ----
    run_gemm<4>(g_wa_hi, g_wa_lo, DN_, smb + K1_A, b0, 0,
                acc, tid, lane, m_base, n_base);

    // prefetch GEMM2 chunk 0 (po2 = (0+4)&1 = 0) during the LayerNorm
    load_B_chunk(g_wb_hi, g_wb_lo, 0, DH_, b0, b0 + BCH, tid);
    CP_COMMIT();

    // ---- LN + ReLU -> A2 tiles (alias A1) ----
    ln_apply(acc, lng, lnb, sm + K1_A, ps, lane, m_base, n_base, warp_n);
    init_bias_reg(acc, b2, lane, n_base);

    // ---- GEMM2: D = H @ W2 (4 chunks, po=0) ----
    run_gemm<4>(g_wb_hi, g_wb_lo, DH_, smb + K1_A, b0, 0,
                acc, tid, lane, m_base, n_base);

    // ---- epilogue: scatter-add to g_agg ----
    #pragma unroll
    for (int mi = 0; mi < 4; mi++) {
        int rl = m_base + mi * 16 + (lane >> 2);
        int rh = rl + 8;
        if (m0 + rl < MM) {
            int e = eid_s[rl];
            #pragma unroll
            for (int ni = 0; ni < 8; ni++) {
                int c = n_base + ni * 8 + 2 * (lane & 3);
                red2(&g_agg[(size_t)e * DH_ + c], acc[mi][ni][0], acc[mi][ni][1]);
            }
        }
        if (m0 + rh < MM) {
            int e = eid_s[rh];
            #pragma unroll
            for (int ni = 0; ni < 8; ni++) {
                int c = n_base + ni * 8 + 2 * (lane & 3);
                red2(&g_agg[(size_t)e * DH_ + c], acc[mi][ni][2], acc[mi][ni][3]);
            }
        }
    }
}

// =====================================================================
// Kernel 2: hyperedge -> node, GEMM1 K = 320
// =====================================================================
__global__ __launch_bounds__(256, 1)
void k_e2n(const int*   __restrict__ node_ids,
           const int*   __restrict__ he_ids,
           const float* __restrict__ he_attr,
           const float* __restrict__ he_count,
           const float* __restrict__ b1,
           const float* __restrict__ lng, const float* __restrict__ lnb,
           const float* __restrict__ b2)
{
    extern __shared__ char sm[];
    const uint32_t smb = s2u(sm);
    const int tid = threadIdx.x, wid = tid >> 5, lane = tid & 31;
    const int warp_m = wid >> 2, warp_n = wid & 3;
    const int m_base = warp_m * 64, n_base = warp_n * 64;
    const int m0 = blockIdx.x * MT;

    int* eid_s = (int*)(sm + K2_EID);
    int* nid_s = (int*)(sm + K2_NID);
    float* rc_s = (float*)(sm + K2_RC);
    float* ps  = (float*)(sm + K2_PS);
    const uint32_t b0 = smb + K2_B0;

    load_B_chunk(g_wc_hi, g_wc_lo, 0, DIN_, b0, b0 + BCH, tid);
    CP_COMMIT();

    if (tid < MT) {
        int m = m0 + tid;
        int mc = m < MM ? m : MM - 1;
        int e = he_ids[mc];
        eid_s[tid] = e;
        nid_s[tid] = node_ids[mc];
        rc_s[tid]  = 1.f / (__ldg(&he_count[e]) + 1e-6f);
    }
    __syncthreads();

    // gather [he_attr | agg/cnt] -> single fp16 swizzled A tiles (5 tiles)
    for (int i = tid; i < MT * 16; i += 256) {            // attr: k 0..63 (tile 0)
        int r = i >> 4, q = i & 15;
        float4 v = __ldg((const float4*)&he_attr[(size_t)eid_s[r] * DHA_ + q * 4]);
        u64 h = (u64)pkh(v.x, v.y) | ((u64)pkh(v.z, v.w) << 32);
        *(u64*)(sm + K2_A + SW128((uint32_t)(r * 128 + q * 8))) = h;
    }
    for (int i = tid; i < MT * 64; i += 256) {            // agg: k 64..319 (tiles 1-4)
        int r = i >> 6, c4 = i & 63;
        float rc = rc_s[r];
        float4 v = *(const float4*)&g_agg[(size_t)eid_s[r] * DH_ + c4 * 4];
        v.x *= rc; v.y *= rc; v.z *= rc; v.w *= rc;
        u64 h = (u64)pkh(v.x, v.y) | ((u64)pkh(v.z, v.w) << 32);
        int k = 64 + c4 * 4, tile = k >> 6, kin = k & 63;
        *(u64*)(sm + K2_A + tile * TILE_B + SW128((uint32_t)(r * 128 + kin * 2))) = h;
    }

    float acc[4][8][4];
    init_bias_reg(acc, b1, lane, n_base);

    // ---- GEMM1: D = [attr|agg] @ W1, K = 320 (5 chunks, po=0) ----
    run_gemm<5>(g_wc_hi, g_wc_lo, DIN_, smb + K2_A, b0, 0,
                acc, tid, lane, m_base, n_base);

    // prefetch GEMM2 chunk 0 (po2 = (0+5)&1 = 1) during the LayerNorm
    load_B_chunk(g_wd_hi, g_wd_lo, 0, DH_, b0 + 2 * BCH, b0 + 3 * BCH, tid);
    CP_COMMIT();

    // ---- LN + ReLU -> A2 tiles (alias A1 tiles 0-3) ----
    ln_apply(acc, lng, lnb, sm + K2_A, ps, lane, m_base, n_base, warp_n);
    init_bias_reg(acc, b2, lane, n_base);

    // ---- GEMM2: D = G @ W2, K = 256 (4 chunks, po=1) ----
    run_gemm<4>(g_wd_hi, g_wd_lo, DH_, smb + K2_A, b0, 1,
                acc, tid, lane, m_base, n_base);

    // ---- epilogue: relu(D) scatter-add to g_acc + degree ----
    #pragma unroll
    for (int mi = 0; mi < 4; mi++) {
        int rl = m_base + mi * 16 + (lane >> 2);
        int rh = rl + 8;
        if (m0 + rl < MM) {
            int n = nid_s[rl];
            #pragma unroll
            for (int ni = 0; ni < 8; ni++) {
                int c = n_base + ni * 8 + 2 * (lane & 3);
                red2(&g_acc[(size_t)n * DN_ + c],
                     fmaxf(acc[mi][ni][0], 0.f), fmaxf(acc[mi][ni][1], 0.f));
            }
            if (warp_n == 0 && (lane & 3) == 0)
                asm volatile("red.global.add.f32 [%0], %1;" :: "l"(&g_deg[n]), "f"(1.f) : "memory");
        }
        if (m0 + rh < MM) {
            int n = nid_s[rh];
            #pragma unroll
            for (int ni = 0; ni < 8; ni++) {
                int c = n_base + ni * 8 + 2 * (lane & 3);
                red2(&g_acc[(size_t)n * DN_ + c],
                     fmaxf(acc[mi][ni][2], 0.f), fmaxf(acc[mi][ni][3], 0.f));
            }
            if (warp_n == 0 && (lane & 3) == 0)
                asm volatile("red.global.add.f32 [%0], %1;" :: "l"(&g_deg[n]), "f"(1.f) : "memory");
        }
    }
}

// =====================================================================
// Kernel 3: out = x + LN(g_acc / (deg + eps)).  Warp per node row.
// =====================================================================
__global__ __launch_bounds__(256, 4)
void k_final(const float* __restrict__ x,
             const float* __restrict__ lng, const float* __restrict__ lnb,
             float* __restrict__ out)
{
    const int lane = threadIdx.x & 31;
    const int n = blockIdx.x * 8 + (threadIdx.x >> 5);
    if (n >= NN) return;

    float rd = 1.f / (g_deg[n] + 1e-6f);
    float v[8], s = 0.f, sq = 0.f;
    #pragma unroll
    for (int j = 0; j < 8; j++) {
        v[j] = g_acc[(size_t)n * DN_ + lane + j * 32] * rd;
        s += v[j]; sq += v[j] * v[j];
    }
    #pragma unroll
    for (int o = 16; o; o >>= 1) {
        s  += __shfl_xor_sync(0xffffffffu, s, o);
        sq += __shfl_xor_sync(0xffffffffu, sq, o);
    }
    float mu = s * (1.f / DN_);
    float var = sq * (1.f / DN_) - mu * mu;
    float rs = rsqrtf(var + 1e-5f);
    #pragma unroll
    for (int j = 0; j < 8; j++) {
        int c = lane + j * 32;
        float t = (v[j] - mu) * rs * __ldg(&lng[c]) + __ldg(&lnb[c]);
        out[(size_t)n * DN_ + c] = __ldg(&x[(size_t)n * DN_ + c]) + t;
    }
}

// =====================================================================
// launcher
// =====================================================================
extern "C" void kernel_launch(void* const* d_in, const int* in_sizes, int n_in,
                              void* d_out, int out_size)
{
    const float* x        = (const float*)d_in[0];
    const int*   node_ids = (const int*)  d_in[1];
    const int*   he_ids   = (const int*)  d_in[2];
    const float* he_attr  = (const float*)d_in[3];
    const float* he_count = (const float*)d_in[4];
    const float* n2e_w1   = (const float*)d_in[5];
    const float* n2e_b1   = (const float*)d_in[6];
    const float* n2e_lng  = (const float*)d_in[7];
    const float* n2e_lnb  = (const float*)d_in[8];
    const float* n2e_w2   = (const float*)d_in[9];
    const float* n2e_b2   = (const float*)d_in[10];
    const float* e2n_w1   = (const float*)d_in[11];
    const float* e2n_b1   = (const float*)d_in[12];
    const float* e2n_lng  = (const float*)d_in[13];
    const float* e2n_lnb  = (const float*)d_in[14];
    const float* e2n_w2   = (const float*)d_in[15];
    const float* e2n_b2   = (const float*)d_in[16];
    const float* ln_g     = (const float*)d_in[17];
    const float* ln_b     = (const float*)d_in[18];
    float* out = (float*)d_out;

    void *p_agg, *p_acc, *p_deg;
    cudaGetSymbolAddress(&p_agg, g_agg);
    cudaGetSymbolAddress(&p_acc, g_acc);
    cudaGetSymbolAddress(&p_deg, g_deg);
    cudaMemsetAsync(p_agg, 0, sizeof(float) * (size_t)EE * DH_);
    cudaMemsetAsync(p_acc, 0, sizeof(float) * (size_t)NN * DN_);
    cudaMemsetAsync(p_deg, 0, sizeof(float) * NN);

    k_prep_all<<<(PREP_TOTAL + 255) / 256, 256>>>(n2e_w1, n2e_w2, e2n_w1, e2n_w2);

    cudaFuncSetAttribute(k_n2e, cudaFuncAttributeMaxDynamicSharedMemorySize, K1_SMEM);
    cudaFuncSetAttribute(k_e2n, cudaFuncAttributeMaxDynamicSharedMemorySize, K2_SMEM);

    k_n2e<<<GRID1, 256, K1_SMEM>>>(x, node_ids, he_ids,
                                   n2e_b1, n2e_lng, n2e_lnb, n2e_b2);
    k_e2n<<<GRID1, 256, K2_SMEM>>>(node_ids, he_ids, he_attr, he_count,
                                   e2n_b1, e2n_lng, e2n_lnb, e2n_b2);
    k_final<<<(NN + 7) / 8, 256>>>(x, ln_g, ln_b, out);
}

// round 11
// speedup vs baseline: 2.2582x; 1.3422x over previous
#include <cuda_runtime.h>
#include <cuda_fp16.h>
#include <cstdint>

// ---------------- problem constants ----------------
#define NN   50000
#define MM   200000
#define EE   10000
#define DN_  256
#define DHA_ 64
#define DH_  256
#define DIN_ 320

#define MT   128          // rows per block
#define KC   64           // K chunk (one SW128 tile)
#define TILE_B (MT * 128) // bytes of one [128][64] fp16 tile = 16384
#define BCH  32768        // bytes of one B chunk [256][64] fp16 (single term)

#define GRID1 ((MM + MT - 1) / MT)   // 1563

typedef unsigned long long u64;

// ---------------- device scratch ----------------
__device__ float g_agg[(size_t)EE * DH_];
__device__ float g_acc[(size_t)NN * DN_];
__device__ float g_deg[NN];

// transposed fp16 weights: [N][K]
__device__ __half g_wa[DN_ * DH_];    // n2e_w1^T [256][256]
__device__ __half g_wb[DH_ * DH_];    // n2e_w2^T [256][256]
__device__ __half g_wc[DH_ * DIN_];   // e2n_w1^T [256][320]
__device__ __half g_wd[DN_ * DH_];    // e2n_w2^T [256][256]

// ---------------- helpers ----------------
__device__ __forceinline__ uint32_t s2u(const void* p) {
    uint32_t a;
    asm("{ .reg .u64 t; cvta.to.shared.u64 t, %1; cvt.u32.u64 %0, t; }" : "=r"(a) : "l"(p));
    return a;
}
#define SW128(x) ((x) ^ ((((x) >> 3) & 0x70)))

__device__ __forceinline__ void ldsm4(uint32_t* r, uint32_t a) {
    asm volatile("ldmatrix.sync.aligned.m8n8.x4.shared.b16 {%0,%1,%2,%3}, [%4];"
        : "=r"(r[0]), "=r"(r[1]), "=r"(r[2]), "=r"(r[3]) : "r"(a));
}
__device__ __forceinline__ void mma16816h(float* d, const uint32_t* a, const uint32_t* b) {
    asm volatile("mma.sync.aligned.m16n8k16.row.col.f32.f16.f16.f32 "
        "{%0,%1,%2,%3}, {%4,%5,%6,%7}, {%8,%9}, {%0,%1,%2,%3};"
        : "+f"(d[0]), "+f"(d[1]), "+f"(d[2]), "+f"(d[3])
        : "r"(a[0]), "r"(a[1]), "r"(a[2]), "r"(a[3]), "r"(b[0]), "r"(b[1]));
}
__device__ __forceinline__ void red2(float* p, float a, float b) {
    asm volatile("red.global.add.v2.f32 [%0], {%1, %2};" :: "l"(p), "f"(a), "f"(b) : "memory");
}
__device__ __forceinline__ void cpa16(uint32_t dst, const void* src) {
    asm volatile("cp.async.cg.shared.global [%0], [%1], 16;" :: "r"(dst), "l"(src) : "memory");
}
#define CP_COMMIT() asm volatile("cp.async.commit_group;" ::: "memory")
#define CP_WAIT2()  asm volatile("cp.async.wait_group 2;" ::: "memory")

// pack 2 floats -> fp16x2 (first arg -> low half / lower address)
__device__ __forceinline__ uint32_t pkh(float lo, float hi) {
    __half2 h = __floats2half2_rn(lo, hi);
    return *reinterpret_cast<uint32_t*>(&h);
}

// ---------------- B chunk load: [256 n][64 k] fp16, coalesced cp.async ----------------
__device__ __forceinline__ void load_B_chunk(const __half* __restrict__ w,
                                             int kc, int kstride,
                                             uint32_t bB, int tid)
{
    #pragma unroll
    for (int it = 0; it < 8; it++) {
        int i = it * 256 + tid;
        int n = i >> 3, q = i & 7;
        size_t src = (size_t)n * kstride + kc * KC + q * 8;
        cpa16(bB + SW128((uint32_t)(n * 128 + q * 16)), w + src);
    }
}

// ---------------- MMA for one k64 chunk (single fp16 term) ----------------
__device__ __forceinline__ void gemm_chunk(uint32_t aT, uint32_t bB,
                                           float (*acc)[8][4],
                                           int lane, int m_base, int n_base)
{
    const uint32_t swz  = (uint32_t)(lane & 7) << 4;
    const uint32_t arow = (uint32_t)(m_base + (lane & 15)) * 128;
    const uint32_t aka  = (uint32_t)((lane >> 4) << 3) * 2;
    const uint32_t brow = (uint32_t)(n_base + ((lane >> 4) << 3) + (lane & 7)) * 128;
    const uint32_t bka  = (uint32_t)(((lane >> 3) & 1) << 3) * 2;

    #pragma unroll
    for (int ks = 0; ks < 4; ks++) {
        const uint32_t koff = (uint32_t)ks * 32;
        const uint32_t aoff = arow + ((koff + aka) ^ swz);
        const uint32_t boff = brow + ((koff + bka) ^ swz);
        uint32_t fa[4][4], fb[4][4];
        #pragma unroll
        for (int mi = 0; mi < 4; mi++) ldsm4(fa[mi], aT + aoff + mi * 2048);
        #pragma unroll
        for (int j = 0; j < 4; j++)  ldsm4(fb[j], bB + boff + j * 2048);
        #pragma unroll
        for (int mi = 0; mi < 4; mi++)
            #pragma unroll
            for (int j = 0; j < 4; j++) {
                mma16816h(acc[mi][2 * j],     fa[mi], fb[j]);
                mma16816h(acc[mi][2 * j + 1], fa[mi], fb[j] + 2);
            }
    }
}

// 4-deep-ring pipelined GEMM over C k64 chunks, ONE sync per chunk.
// buf(c) = b0 + ((po + c) & 3) * BCH.
// Prologue: chunks 0..2 must already be issued, one commit each (3 groups).
// Iter c: wait_group 2 (chunk c's group retired, groups retire in order),
// sync (all warps done reading buf (c-1)&3 => safe to overwrite buf (c+3)&3),
// issue load c+3 + commit, compute chunk c.
template<int C>
__device__ __forceinline__ void run_gemm(const __half* __restrict__ w, int kstride,
                                         uint32_t aBase, uint32_t b0, int po,
                                         float (*acc)[8][4],
                                         int tid, int lane, int m_base, int n_base)
{
    #pragma unroll 1
    for (int c = 0; c < C; c++) {
        CP_WAIT2();
        __syncthreads();
        if (c + 3 < C)
            load_B_chunk(w, c + 3, kstride, b0 + (uint32_t)((po + c + 3) & 3) * BCH, tid);
        CP_COMMIT();
        gemm_chunk(aBase + c * TILE_B, b0 + (uint32_t)((po + c) & 3) * BCH,
                   acc, lane, m_base, n_base);
    }
}

// prologue: issue chunks 0..2, one commit group each
__device__ __forceinline__ void prologue_B(const __half* __restrict__ w, int kstride,
                                           uint32_t b0, int po, int tid)
{
    #pragma unroll
    for (int c = 0; c < 3; c++) {
        load_B_chunk(w, c, kstride, b0 + (uint32_t)((po + c) & 3) * BCH, tid);
        CP_COMMIT();
    }
}

__device__ __forceinline__ void init_bias_reg(float (*acc)[8][4],
                                              const float* __restrict__ b,
                                              int lane, int n_base)
{
    #pragma unroll
    for (int ni = 0; ni < 8; ni++) {
        int c = n_base + ni * 8 + 2 * (lane & 3);
        float v0 = __ldg(&b[c]), v1 = __ldg(&b[c + 1]);
        #pragma unroll
        for (int mi = 0; mi < 4; mi++) {
            acc[mi][ni][0] = v0; acc[mi][ni][1] = v1;
            acc[mi][ni][2] = v0; acc[mi][ni][3] = v1;
        }
    }
}

// LayerNorm + ReLU on register accumulators -> single fp16 A2 smem tiles.
__device__ __forceinline__ void ln_apply(float (*acc)[8][4],
                                         const float* __restrict__ lng,
                                         const float* __restrict__ lnb,
                                         char* a2, float* ps,
                                         int lane, int m_base, int n_base, int warp_n)
{
    #pragma unroll
    for (int mi = 0; mi < 4; mi++) {
        float sl = 0.f, ql = 0.f, sh = 0.f, qh = 0.f;
        #pragma unroll
        for (int ni = 0; ni < 8; ni++) {
            float a0 = acc[mi][ni][0], a1 = acc[mi][ni][1];
            float a2v = acc[mi][ni][2], a3 = acc[mi][ni][3];
            sl += a0 + a1; ql += a0 * a0 + a1 * a1;
            sh += a2v + a3; qh += a2v * a2v + a3 * a3;
        }
        sl += __shfl_xor_sync(0xffffffffu, sl, 1); sl += __shfl_xor_sync(0xffffffffu, sl, 2);
        ql += __shfl_xor_sync(0xffffffffu, ql, 1); ql += __shfl_xor_sync(0xffffffffu, ql, 2);
        sh += __shfl_xor_sync(0xffffffffu, sh, 1); sh += __shfl_xor_sync(0xffffffffu, sh, 2);
        qh += __shfl_xor_sync(0xffffffffu, qh, 1); qh += __shfl_xor_sync(0xffffffffu, qh, 2);
        if ((lane & 3) == 0) {
            int rl = m_base + mi * 16 + (lane >> 2);
            ps[rl * 4 + warp_n] = sl;        ps[512 + rl * 4 + warp_n] = ql;
            ps[(rl + 8) * 4 + warp_n] = sh;  ps[512 + (rl + 8) * 4 + warp_n] = qh;
        }
    }
    __syncthreads();
    float mu[4][2], rsd[4][2];
    #pragma unroll
    for (int mi = 0; mi < 4; mi++) {
        int rl = m_base + mi * 16 + (lane >> 2);
        #pragma unroll
        for (int h = 0; h < 2; h++) {
            int r = rl + h * 8;
            float s = ps[r * 4] + ps[r * 4 + 1] + ps[r * 4 + 2] + ps[r * 4 + 3];
            float q = ps[512 + r * 4] + ps[512 + r * 4 + 1] + ps[512 + r * 4 + 2] + ps[512 + r * 4 + 3];
            float m = s * (1.f / 256.f);
            float var = q * (1.f / 256.f) - m * m;
            mu[mi][h] = m;
            rsd[mi][h] = rsqrtf(var + 1e-5f);
        }
    }
    __syncthreads();
    #pragma unroll
    for (int mi = 0; mi < 4; mi++) {
        int rl = m_base + mi * 16 + (lane >> 2);
        int rh = rl + 8;
        uint32_t rswz = (uint32_t)(lane >> 2) << 4;
        #pragma unroll
        for (int ni = 0; ni < 8; ni++) {
            int cl = ni * 8 + 2 * (lane & 3);
            int c  = n_base + cl;
            float g0 = __ldg(&lng[c]),  g1 = __ldg(&lng[c + 1]);
            float B0 = __ldg(&lnb[c]),  B1 = __ldg(&lnb[c + 1]);
            uint32_t kb = ((uint32_t)(cl * 2)) ^ rswz;
            {
                float t0 = fmaxf((acc[mi][ni][0] - mu[mi][0]) * rsd[mi][0] * g0 + B0, 0.f);
                float t1 = fmaxf((acc[mi][ni][1] - mu[mi][0]) * rsd[mi][0] * g1 + B1, 0.f);
                *(uint32_t*)(a2 + (uint32_t)warp_n * TILE_B + (uint32_t)rl * 128 + kb) = pkh(t0, t1);
            }
            {
                float t0 = fmaxf((acc[mi][ni][2] - mu[mi][1]) * rsd[mi][1] * g0 + B0, 0.f);
                float t1 = fmaxf((acc[mi][ni][3] - mu[mi][1]) * rsd[mi][1] * g1 + B1, 0.f);
                *(uint32_t*)(a2 + (uint32_t)warp_n * TILE_B + (uint32_t)rh * 128 + kb) = pkh(t0, t1);
            }
        }
    }
}

// ---------------- prep: all 4 weights -> transposed fp16 [N][K] ----------------
#define PREP_TOTAL (65536 + 65536 + 81920 + 65536)
__global__ void k_prep_all(const float* __restrict__ wa, const float* __restrict__ wb,
                           const float* __restrict__ wc, const float* __restrict__ wd)
{
    int i = blockIdx.x * 256 + threadIdx.x;
    if (i >= PREP_TOTAL) return;
    const float* w; __half* th; int K, N, j;
    if (i < 65536)       { w = wa; th = g_wa; K = 256; N = 256; j = i; }
    else if (i < 131072) { w = wb; th = g_wb; K = 256; N = 256; j = i - 65536; }
    else if (i < 212992) { w = wc; th = g_wc; K = 320; N = 256; j = i - 131072; }
    else                 { w = wd; th = g_wd; K = 256; N = 256; j = i - 212992; }
    int n = j / K, k = j - n * K;
    th[j] = __float2half(__ldg(&w[(size_t)k * N + n]));
}

// ---------------- smem offsets ----------------
// K1: A 4 fp16 tiles (64K), B ring 4x32K (128K), ps 4K, ids
#define K1_A   0
#define K1_B0  65536
#define K1_PS  196608
#define K1_EID 200704
#define K1_NID 201216
#define K1_SMEM 201728

// K2: A 5 fp16 tiles (80K), B ring 4x32K (128K), ps 4K, ids
#define K2_A   0
#define K2_B0  81920
#define K2_PS  212992
#define K2_EID 217088
#define K2_NID 217600
#define K2_RC  218112
#define K2_SMEM 218656

// =====================================================================
// Kernel 1: node -> hyperedge
// =====================================================================
__global__ __launch_bounds__(256, 1)
void k_n2e(const float* __restrict__ x,
           const int*   __restrict__ node_ids,
           const int*   __restrict__ he_ids,
           const float* __restrict__ b1,
           const float* __restrict__ lng, const float* __restrict__ lnb,
           const float* __restrict__ b2)
{
    extern __shared__ char sm[];
    const uint32_t smb = s2u(sm);
    const int tid = threadIdx.x, wid = tid >> 5, lane = tid & 31;
    const int warp_m = wid >> 2, warp_n = wid & 3;
    const int m_base = warp_m * 64, n_base = warp_n * 64;
    const int m0 = blockIdx.x * MT;

    int* eid_s = (int*)(sm + K1_EID);
    int* nid_s = (int*)(sm + K1_NID);
    float* ps  = (float*)(sm + K1_PS);
    const uint32_t b0 = smb + K1_B0;

    // GEMM1 prologue: chunks 0..2 (overlaps the A gather)
    prologue_B(g_wa, DN_, b0, 0, tid);

    if (tid < MT) {
        int m = m0 + tid;
        int mc = m < MM ? m : MM - 1;
        eid_s[tid] = he_ids[mc];
        nid_s[tid] = node_ids[mc];
    }
    __syncthreads();

    // gather x -> single fp16 swizzled A tiles
    for (int i = tid; i < MT * 64; i += 256) {
        int r = i >> 6, c4 = i & 63;
        float4 v = __ldg((const float4*)&x[(size_t)nid_s[r] * DN_ + c4 * 4]);
        u64 h = (u64)pkh(v.x, v.y) | ((u64)pkh(v.z, v.w) << 32);
        int k = c4 * 4, tile = k >> 6, kin = k & 63;
        *(u64*)(sm + K1_A + tile * TILE_B + SW128((uint32_t)(r * 128 + kin * 2))) = h;
    }

    float acc[4][8][4];
    init_bias_reg(acc, b1, lane, n_base);

    // ---- GEMM1: D = X @ W1 (4 chunks, po=0) ----
    run_gemm<4>(g_wa, DN_, smb + K1_A, b0, 0, acc, tid, lane, m_base, n_base);

    // prefetch GEMM2 chunks 0..2 (po2 = (0+4)&3 = 0) during the LayerNorm
    prologue_B(g_wb, DH_, b0, 0, tid);

    // ---- LN + ReLU -> A2 tiles (alias A1) ----
    ln_apply(acc, lng, lnb, sm + K1_A, ps, lane, m_base, n_base, warp_n);
    init_bias_reg(acc, b2, lane, n_base);

    // ---- GEMM2: D = H @ W2 (4 chunks, po=0) ----
    run_gemm<4>(g_wb, DH_, smb + K1_A, b0, 0, acc, tid, lane, m_base, n_base);

    // ---- epilogue: scatter-add to g_agg ----
    #pragma unroll
    for (int mi = 0; mi < 4; mi++) {
        int rl = m_base + mi * 16 + (lane >> 2);
        int rh = rl + 8;
        if (m0 + rl < MM) {
            int e = eid_s[rl];
            #pragma unroll
            for (int ni = 0; ni < 8; ni++) {
                int c = n_base + ni * 8 + 2 * (lane & 3);
                red2(&g_agg[(size_t)e * DH_ + c], acc[mi][ni][0], acc[mi][ni][1]);
            }
        }
        if (m0 + rh < MM) {
            int e = eid_s[rh];
            #pragma unroll
            for (int ni = 0; ni < 8; ni++) {
                int c = n_base + ni * 8 + 2 * (lane & 3);
                red2(&g_agg[(size_t)e * DH_ + c], acc[mi][ni][2], acc[mi][ni][3]);
            }
        }
    }
}

// =====================================================================
// Kernel 2: hyperedge -> node, GEMM1 K = 320
// =====================================================================
__global__ __launch_bounds__(256, 1)
void k_e2n(const int*   __restrict__ node_ids,
           const int*   __restrict__ he_ids,
           const float* __restrict__ he_attr,
           const float* __restrict__ he_count,
           const float* __restrict__ b1,
           const float* __restrict__ lng, const float* __restrict__ lnb,
           const float* __restrict__ b2)
{
    extern __shared__ char sm[];
    const uint32_t smb = s2u(sm);
    const int tid = threadIdx.x, wid = tid >> 5, lane = tid & 31;
    const int warp_m = wid >> 2, warp_n = wid & 3;
    const int m_base = warp_m * 64, n_base = warp_n * 64;
    const int m0 = blockIdx.x * MT;

    int* eid_s = (int*)(sm + K2_EID);
    int* nid_s = (int*)(sm + K2_NID);
    float* rc_s = (float*)(sm + K2_RC);
    float* ps  = (float*)(sm + K2_PS);
    const uint32_t b0 = smb + K2_B0;

    prologue_B(g_wc, DIN_, b0, 0, tid);

    if (tid < MT) {
        int m = m0 + tid;
        int mc = m < MM ? m : MM - 1;
        int e = he_ids[mc];
        eid_s[tid] = e;
        nid_s[tid] = node_ids[mc];
        rc_s[tid]  = 1.f / (__ldg(&he_count[e]) + 1e-6f);
    }
    __syncthreads();

    // gather [he_attr | agg/cnt] -> single fp16 swizzled A tiles (5 tiles)
    for (int i = tid; i < MT * 16; i += 256) {            // attr: k 0..63 (tile 0)
        int r = i >> 4, q = i & 15;
        float4 v = __ldg((const float4*)&he_attr[(size_t)eid_s[r] * DHA_ + q * 4]);
        u64 h = (u64)pkh(v.x, v.y) | ((u64)pkh(v.z, v.w) << 32);
        *(u64*)(sm + K2_A + SW128((uint32_t)(r * 128 + q * 8))) = h;
    }
    for (int i = tid; i < MT * 64; i += 256) {            // agg: k 64..319 (tiles 1-4)
        int r = i >> 6, c4 = i & 63;
        float rc = rc_s[r];
        float4 v = *(const float4*)&g_agg[(size_t)eid_s[r] * DH_ + c4 * 4];
        v.x *= rc; v.y *= rc; v.z *= rc; v.w *= rc;
        u64 h = (u64)pkh(v.x, v.y) | ((u64)pkh(v.z, v.w) << 32);
        int k = 64 + c4 * 4, tile = k >> 6, kin = k & 63;
        *(u64*)(sm + K2_A + tile * TILE_B + SW128((uint32_t)(r * 128 + kin * 2))) = h;
    }

    float acc[4][8][4];
    init_bias_reg(acc, b1, lane, n_base);

    // ---- GEMM1: D = [attr|agg] @ W1, K = 320 (5 chunks, po=0) ----
    run_gemm<5>(g_wc, DIN_, smb + K2_A, b0, 0, acc, tid, lane, m_base, n_base);

    // prefetch GEMM2 chunks 0..2 (po2 = (0+5)&3 = 1) during the LayerNorm
    prologue_B(g_wd, DH_, b0, 1, tid);

    // ---- LN + ReLU -> A2 tiles (alias A1 tiles 0-3) ----
    ln_apply(acc, lng, lnb, sm + K2_A, ps, lane, m_base, n_base, warp_n);
    init_bias_reg(acc, b2, lane, n_base);

    // ---- GEMM2: D = G @ W2, K = 256 (4 chunks, po=1) ----
    run_gemm<4>(g_wd, DH_, smb + K2_A, b0, 1, acc, tid, lane, m_base, n_base);

    // ---- epilogue: relu(D) scatter-add to g_acc + degree ----
    #pragma unroll
    for (int mi = 0; mi < 4; mi++) {
        int rl = m_base + mi * 16 + (lane >> 2);
        int rh = rl + 8;
        if (m0 + rl < MM) {
            int n = nid_s[rl];
            #pragma unroll
            for (int ni = 0; ni < 8; ni++) {
                int c = n_base + ni * 8 + 2 * (lane & 3);
                red2(&g_acc[(size_t)n * DN_ + c],
                     fmaxf(acc[mi][ni][0], 0.f), fmaxf(acc[mi][ni][1], 0.f));
            }
            if (warp_n == 0 && (lane & 3) == 0)
                asm volatile("red.global.add.f32 [%0], %1;" :: "l"(&g_deg[n]), "f"(1.f) : "memory");
        }
        if (m0 + rh < MM) {
            int n = nid_s[rh];
            #pragma unroll
            for (int ni = 0; ni < 8; ni++) {
                int c = n_base + ni * 8 + 2 * (lane & 3);
                red2(&g_acc[(size_t)n * DN_ + c],
                     fmaxf(acc[mi][ni][2], 0.f), fmaxf(acc[mi][ni][3], 0.f));
            }
            if (warp_n == 0 && (lane & 3) == 0)
                asm volatile("red.global.add.f32 [%0], %1;" :: "l"(&g_deg[n]), "f"(1.f) : "memory");
        }
    }
}

// =====================================================================
// Kernel 3: out = x + LN(g_acc / (deg + eps)).  Warp per node row.
// =====================================================================
__global__ __launch_bounds__(256, 4)
void k_final(const float* __restrict__ x,
             const float* __restrict__ lng, const float* __restrict__ lnb,
             float* __restrict__ out)
{
    const int lane = threadIdx.x & 31;
    const int n = blockIdx.x * 8 + (threadIdx.x >> 5);
    if (n >= NN) return;

    float rd = 1.f / (g_deg[n] + 1e-6f);
    float v[8], s = 0.f, sq = 0.f;
    #pragma unroll
    for (int j = 0; j < 8; j++) {
        v[j] = g_acc[(size_t)n * DN_ + lane + j * 32] * rd;
        s += v[j]; sq += v[j] * v[j];
    }
    #pragma unroll
    for (int o = 16; o; o >>= 1) {
        s  += __shfl_xor_sync(0xffffffffu, s, o);
        sq += __shfl_xor_sync(0xffffffffu, sq, o);
    }
    float mu = s * (1.f / DN_);
    float var = sq * (1.f / DN_) - mu * mu;
    float rs = rsqrtf(var + 1e-5f);
    #pragma unroll
    for (int j = 0; j < 8; j++) {
        int c = lane + j * 32;
        float t = (v[j] - mu) * rs * __ldg(&lng[c]) + __ldg(&lnb[c]);
        out[(size_t)n * DN_ + c] = __ldg(&x[(size_t)n * DN_ + c]) + t;
    }
}

// =====================================================================
// launcher
// =====================================================================
extern "C" void kernel_launch(void* const* d_in, const int* in_sizes, int n_in,
                              void* d_out, int out_size)
{
    const float* x        = (const float*)d_in[0];
    const int*   node_ids = (const int*)  d_in[1];
    const int*   he_ids   = (const int*)  d_in[2];
    const float* he_attr  = (const float*)d_in[3];
    const float* he_count = (const float*)d_in[4];
    const float* n2e_w1   = (const float*)d_in[5];
    const float* n2e_b1   = (const float*)d_in[6];
    const float* n2e_lng  = (const float*)d_in[7];
    const float* n2e_lnb  = (const float*)d_in[8];
    const float* n2e_w2   = (const float*)d_in[9];
    const float* n2e_b2   = (const float*)d_in[10];
    const float* e2n_w1   = (const float*)d_in[11];
    const float* e2n_b1   = (const float*)d_in[12];
    const float* e2n_lng  = (const float*)d_in[13];
    const float* e2n_lnb  = (const float*)d_in[14];
    const float* e2n_w2   = (const float*)d_in[15];
    const float* e2n_b2   = (const float*)d_in[16];
    const float* ln_g     = (const float*)d_in[17];
    const float* ln_b     = (const float*)d_in[18];
    float* out = (float*)d_out;

    void *p_agg, *p_acc, *p_deg;
    cudaGetSymbolAddress(&p_agg, g_agg);
    cudaGetSymbolAddress(&p_acc, g_acc);
    cudaGetSymbolAddress(&p_deg, g_deg);
    cudaMemsetAsync(p_agg, 0, sizeof(float) * (size_t)EE * DH_);
    cudaMemsetAsync(p_acc, 0, sizeof(float) * (size_t)NN * DN_);
    cudaMemsetAsync(p_deg, 0, sizeof(float) * NN);

    k_prep_all<<<(PREP_TOTAL + 255) / 256, 256>>>(n2e_w1, n2e_w2, e2n_w1, e2n_w2);

    cudaFuncSetAttribute(k_n2e, cudaFuncAttributeMaxDynamicSharedMemorySize, K1_SMEM);
    cudaFuncSetAttribute(k_e2n, cudaFuncAttributeMaxDynamicSharedMemorySize, K2_SMEM);

    k_n2e<<<GRID1, 256, K1_SMEM>>>(x, node_ids, he_ids,
                                   n2e_b1, n2e_lng, n2e_lnb, n2e_b2);
    k_e2n<<<GRID1, 256, K2_SMEM>>>(node_ids, he_ids, he_attr, he_count,
                                   e2n_b1, e2n_lng, e2n_lnb, e2n_b2);
    k_final<<<(NN + 7) / 8, 256>>>(x, ln_g, ln_b, out);
}

// round 13
// speedup vs baseline: 2.3203x; 1.0275x over previous
#include <cuda_runtime.h>
#include <cuda_fp16.h>
#include <cstdint>

// ---------------- problem constants ----------------
#define NN   50000
#define MM   200000
#define EE   10000
#define DN_  256
#define DHA_ 64
#define DH_  256
#define DIN_ 320

#define MT   128          // rows per block
#define KC   64           // K chunk (one SW128 tile)
#define TILE_B (MT * 128) // bytes of one [128][64] fp16 tile = 16384
#define BCH  32768        // bytes of one B chunk [256][64] fp16
#define SP   264          // stage pitch in floats (bank-conflict padding)

#define GRID1 ((MM + MT - 1) / MT)   // 1563

typedef unsigned long long u64;

// ---------------- device scratch ----------------
__device__ float g_agg[(size_t)EE * DH_];
__device__ float g_acc[(size_t)NN * DN_];
__device__ float g_deg[NN];

// transposed fp16 weights: [N][K]
__device__ __half g_wa[DN_ * DH_];    // n2e_w1^T [256][256]
__device__ __half g_wb[DH_ * DH_];    // n2e_w2^T [256][256]
__device__ __half g_wc[DH_ * DIN_];   // e2n_w1^T [256][320]
__device__ __half g_wd[DN_ * DH_];    // e2n_w2^T [256][256]

// ---------------- helpers ----------------
__device__ __forceinline__ uint32_t s2u(const void* p) {
    uint32_t a;
    asm("{ .reg .u64 t; cvta.to.shared.u64 t, %1; cvt.u32.u64 %0, t; }" : "=r"(a) : "l"(p));
    return a;
}
#define SW128(x) ((x) ^ ((((x) >> 3) & 0x70)))

__device__ __forceinline__ void ldsm4(uint32_t* r, uint32_t a) {
    asm volatile("ldmatrix.sync.aligned.m8n8.x4.shared.b16 {%0,%1,%2,%3}, [%4];"
        : "=r"(r[0]), "=r"(r[1]), "=r"(r[2]), "=r"(r[3]) : "r"(a));
}
__device__ __forceinline__ void mma16816h(float* d, const uint32_t* a, const uint32_t* b) {
    asm volatile("mma.sync.aligned.m16n8k16.row.col.f32.f16.f16.f32 "
        "{%0,%1,%2,%3}, {%4,%5,%6,%7}, {%8,%9}, {%0,%1,%2,%3};"
        : "+f"(d[0]), "+f"(d[1]), "+f"(d[2]), "+f"(d[3])
        : "r"(a[0]), "r"(a[1]), "r"(a[2]), "r"(a[3]), "r"(b[0]), "r"(b[1]));
}
__device__ __forceinline__ void red4(float* p, float a, float b, float c, float d) {
    asm volatile("red.global.add.v4.f32 [%0], {%1, %2, %3, %4};"
                 :: "l"(p), "f"(a), "f"(b), "f"(c), "f"(d) : "memory");
}
__device__ __forceinline__ void cpa16(uint32_t dst, const void* src) {
    asm volatile("cp.async.cg.shared.global [%0], [%1], 16;" :: "r"(dst), "l"(src) : "memory");
}
#define CP_COMMIT() asm volatile("cp.async.commit_group;" ::: "memory")
#define CP_WAIT2()  asm volatile("cp.async.wait_group 2;" ::: "memory")

// pack 2 floats -> fp16x2 (first arg -> low half / lower address)
__device__ __forceinline__ uint32_t pkh(float lo, float hi) {
    __half2 h = __floats2half2_rn(lo, hi);
    return *reinterpret_cast<uint32_t*>(&h);
}

// ---------------- B chunk load: [256 n][64 k] fp16, coalesced cp.async ----------------
__device__ __forceinline__ void load_B_chunk(const __half* __restrict__ w,
                                             int kc, int kstride,
                                             uint32_t bB, int tid)
{
    #pragma unroll
    for (int it = 0; it < 8; it++) {
        int i = it * 256 + tid;
        int n = i >> 3, q = i & 7;
        size_t src = (size_t)n * kstride + kc * KC + q * 8;
        cpa16(bB + SW128((uint32_t)(n * 128 + q * 16)), w + src);
    }
}

// ---------------- MMA for one k64 chunk (single fp16 term) ----------------
__device__ __forceinline__ void gemm_chunk(uint32_t aT, uint32_t bB,
                                           float (*acc)[8][4],
                                           int lane, int m_base, int n_base)
{
    const uint32_t swz  = (uint32_t)(lane & 7) << 4;
    const uint32_t arow = (uint32_t)(m_base + (lane & 15)) * 128;
    const uint32_t aka  = (uint32_t)((lane >> 4) << 3) * 2;
    const uint32_t brow = (uint32_t)(n_base + ((lane >> 4) << 3) + (lane & 7)) * 128;
    const uint32_t bka  = (uint32_t)(((lane >> 3) & 1) << 3) * 2;

    #pragma unroll
    for (int ks = 0; ks < 4; ks++) {
        const uint32_t koff = (uint32_t)ks * 32;
        const uint32_t aoff = arow + ((koff + aka) ^ swz);
        const uint32_t boff = brow + ((koff + bka) ^ swz);
        uint32_t fa[4][4], fb[4][4];
        #pragma unroll
        for (int mi = 0; mi < 4; mi++) ldsm4(fa[mi], aT + aoff + mi * 2048);
        #pragma unroll
        for (int j = 0; j < 4; j++)  ldsm4(fb[j], bB + boff + j * 2048);
        #pragma unroll
        for (int mi = 0; mi < 4; mi++)
            #pragma unroll
            for (int j = 0; j < 4; j++) {
                mma16816h(acc[mi][2 * j],     fa[mi], fb[j]);
                mma16816h(acc[mi][2 * j + 1], fa[mi], fb[j] + 2);
            }
    }
}

// 4-deep-ring pipelined GEMM over C k64 chunks, ONE sync per chunk.
template<int C>
__device__ __forceinline__ void run_gemm(const __half* __restrict__ w, int kstride,
                                         uint32_t aBase, uint32_t b0, int po,
                                         float (*acc)[8][4],
                                         int tid, int lane, int m_base, int n_base)
{
    #pragma unroll 1
    for (int c = 0; c < C; c++) {
        CP_WAIT2();
        __syncthreads();
        if (c + 3 < C)
            load_B_chunk(w, c + 3, kstride, b0 + (uint32_t)((po + c + 3) & 3) * BCH, tid);
        CP_COMMIT();
        gemm_chunk(aBase + c * TILE_B, b0 + (uint32_t)((po + c) & 3) * BCH,
                   acc, lane, m_base, n_base);
    }
}

// prologue: issue chunks 0..2, one commit group each
__device__ __forceinline__ void prologue_B(const __half* __restrict__ w, int kstride,
                                           uint32_t b0, int po, int tid)
{
    #pragma unroll
    for (int c = 0; c < 3; c++) {
        load_B_chunk(w, c, kstride, b0 + (uint32_t)((po + c) & 3) * BCH, tid);
        CP_COMMIT();
    }
}

__device__ __forceinline__ void init_bias_reg(float (*acc)[8][4],
                                              const float* __restrict__ b,
                                              int lane, int n_base)
{
    #pragma unroll
    for (int ni = 0; ni < 8; ni++) {
        int c = n_base + ni * 8 + 2 * (lane & 3);
        float v0 = __ldg(&b[c]), v1 = __ldg(&b[c + 1]);
        #pragma unroll
        for (int mi = 0; mi < 4; mi++) {
            acc[mi][ni][0] = v0; acc[mi][ni][1] = v1;
            acc[mi][ni][2] = v0; acc[mi][ni][3] = v1;
        }
    }
}

// LayerNorm + ReLU on register accumulators -> single fp16 A2 smem tiles.
__device__ __forceinline__ void ln_apply(float (*acc)[8][4],
                                         const float* __restrict__ lng,
                                         const float* __restrict__ lnb,
                                         char* a2, float* ps,
                                         int lane, int m_base, int n_base, int warp_n)
{
    #pragma unroll
    for (int mi = 0; mi < 4; mi++) {
        float sl = 0.f, ql = 0.f, sh = 0.f, qh = 0.f;
        #pragma unroll
        for (int ni = 0; ni < 8; ni++) {
            float a0 = acc[mi][ni][0], a1 = acc[mi][ni][1];
            float a2v = acc[mi][ni][2], a3 = acc[mi][ni][3];
            sl += a0 + a1; ql += a0 * a0 + a1 * a1;
            sh += a2v + a3; qh += a2v * a2v + a3 * a3;
        }
        sl += __shfl_xor_sync(0xffffffffu, sl, 1); sl += __shfl_xor_sync(0xffffffffu, sl, 2);
        ql += __shfl_xor_sync(0xffffffffu, ql, 1); ql += __shfl_xor_sync(0xffffffffu, ql, 2);
        sh += __shfl_xor_sync(0xffffffffu, sh, 1); sh += __shfl_xor_sync(0xffffffffu, sh, 2);
        qh += __shfl_xor_sync(0xffffffffu, qh, 1); qh += __shfl_xor_sync(0xffffffffu, qh, 2);
        if ((lane & 3) == 0) {
            int rl = m_base + mi * 16 + (lane >> 2);
            ps[rl * 4 + warp_n] = sl;        ps[512 + rl * 4 + warp_n] = ql;
            ps[(rl + 8) * 4 + warp_n] = sh;  ps[512 + (rl + 8) * 4 + warp_n] = qh;
        }
    }
    __syncthreads();
    float mu[4][2], rsd[4][2];
    #pragma unroll
    for (int mi = 0; mi < 4; mi++) {
        int rl = m_base + mi * 16 + (lane >> 2);
        #pragma unroll
        for (int h = 0; h < 2; h++) {
            int r = rl + h * 8;
            float s = ps[r * 4] + ps[r * 4 + 1] + ps[r * 4 + 2] + ps[r * 4 + 3];
            float q = ps[512 + r * 4] + ps[512 + r * 4 + 1] + ps[512 + r * 4 + 2] + ps[512 + r * 4 + 3];
            float m = s * (1.f / 256.f);
            float var = q * (1.f / 256.f) - m * m;
            mu[mi][h] = m;
            rsd[mi][h] = rsqrtf(var + 1e-5f);
        }
    }
    __syncthreads();
    #pragma unroll
    for (int mi = 0; mi < 4; mi++) {
        int rl = m_base + mi * 16 + (lane >> 2);
        int rh = rl + 8;
        uint32_t rswz = (uint32_t)(lane >> 2) << 4;
        #pragma unroll
        for (int ni = 0; ni < 8; ni++) {
            int cl = ni * 8 + 2 * (lane & 3);
            int c  = n_base + cl;
            float g0 = __ldg(&lng[c]),  g1 = __ldg(&lng[c + 1]);
            float B0 = __ldg(&lnb[c]),  B1 = __ldg(&lnb[c + 1]);
            uint32_t kb = ((uint32_t)(cl * 2)) ^ rswz;
            {
                float t0 = fmaxf((acc[mi][ni][0] - mu[mi][0]) * rsd[mi][0] * g0 + B0, 0.f);
                float t1 = fmaxf((acc[mi][ni][1] - mu[mi][0]) * rsd[mi][0] * g1 + B1, 0.f);
                *(uint32_t*)(a2 + (uint32_t)warp_n * TILE_B + (uint32_t)rl * 128 + kb) = pkh(t0, t1);
            }
            {
                float t0 = fmaxf((acc[mi][ni][2] - mu[mi][1]) * rsd[mi][1] * g0 + B0, 0.f);
                float t1 = fmaxf((acc[mi][ni][3] - mu[mi][1]) * rsd[mi][1] * g1 + B1, 0.f);
                *(uint32_t*)(a2 + (uint32_t)warp_n * TILE_B + (uint32_t)rh * 128 + kb) = pkh(t0, t1);
            }
        }
    }
}

// stage acc (bias already included) into fp32 smem tile [128][SP]
__device__ __forceinline__ void stage_acc(float (*acc)[8][4], float* stg,
                                          int lane, int m_base, int n_base)
{
    #pragma unroll
    for (int mi = 0; mi < 4; mi++) {
        int rl = m_base + mi * 16 + (lane >> 2);
        int rh = rl + 8;
        #pragma unroll
        for (int ni = 0; ni < 8; ni++) {
            int col = n_base + ni * 8 + 2 * (lane & 3);
            *(float2*)&stg[rl * SP + col] = make_float2(acc[mi][ni][0], acc[mi][ni][1]);
            *(float2*)&stg[rh * SP + col] = make_float2(acc[mi][ni][2], acc[mi][ni][3]);
        }
    }
}

// ---------------- prep: all 4 weights -> transposed fp16 [N][K] ----------------
#define PREP_TOTAL (65536 + 65536 + 81920 + 65536)
__global__ void k_prep_all(const float* __restrict__ wa, const float* __restrict__ wb,
                           const float* __restrict__ wc, const float* __restrict__ wd)
{
    int i = blockIdx.x * 256 + threadIdx.x;
    if (i >= PREP_TOTAL) return;
    const float* w; __half* th; int K, N, j;
    if (i < 65536)       { w = wa; th = g_wa; K = 256; N = 256; j = i; }
    else if (i < 131072) { w = wb; th = g_wb; K = 256; N = 256; j = i - 65536; }
    else if (i < 212992) { w = wc; th = g_wc; K = 320; N = 256; j = i - 131072; }
    else                 { w = wd; th = g_wd; K = 256; N = 256; j = i - 212992; }
    int n = j / K, k = j - n * K;
    th[j] = __float2half(__ldg(&w[(size_t)k * N + n]));
}

// ---------------- smem offsets ----------------
// stage tile (fp32 [128][SP] = 135168 B) aliases A tiles + B ring (both dead post-GEMM2)
#define K1_A   0
#define K1_B0  65536
#define K1_PS  196608
#define K1_EID 200704
#define K1_NID 201216
#define K1_SMEM 201728

#define K2_A   0
#define K2_B0  81920
#define K2_PS  212992
#define K2_EID 217088
#define K2_NID 217600
#define K2_RC  218112
#define K2_SMEM 218656

// =====================================================================
// Kernel 1: node -> hyperedge
// =====================================================================
__global__ __launch_bounds__(256, 1)
void k_n2e(const float* __restrict__ x,
           const int*   __restrict__ node_ids,
           const int*   __restrict__ he_ids,
           const float* __restrict__ b1,
           const float* __restrict__ lng, const float* __restrict__ lnb,
           const float* __restrict__ b2)
{
    extern __shared__ char sm[];
    const uint32_t smb = s2u(sm);
    const int tid = threadIdx.x, wid = tid >> 5, lane = tid & 31;
    const int warp_m = wid >> 2, warp_n = wid & 3;
    const int m_base = warp_m * 64, n_base = warp_n * 64;
    const int m0 = blockIdx.x * MT;

    int* eid_s = (int*)(sm + K1_EID);
    int* nid_s = (int*)(sm + K1_NID);
    float* ps  = (float*)(sm + K1_PS);
    float* stg = (float*)sm;
    const uint32_t b0 = smb + K1_B0;

    prologue_B(g_wa, DN_, b0, 0, tid);

    if (tid < MT) {
        int m = m0 + tid;
        int mc = m < MM ? m : MM - 1;
        eid_s[tid] = he_ids[mc];
        nid_s[tid] = node_ids[mc];
    }
    __syncthreads();

    // gather x -> single fp16 swizzled A tiles
    for (int i = tid; i < MT * 64; i += 256) {
        int r = i >> 6, c4 = i & 63;
        float4 v = __ldg((const float4*)&x[(size_t)nid_s[r] * DN_ + c4 * 4]);
        u64 h = (u64)pkh(v.x, v.y) | ((u64)pkh(v.z, v.w) << 32);
        int k = c4 * 4, tile = k >> 6, kin = k & 63;
        *(u64*)(sm + K1_A + tile * TILE_B + SW128((uint32_t)(r * 128 + kin * 2))) = h;
    }

    float acc[4][8][4];
    init_bias_reg(acc, b1, lane, n_base);

    // ---- GEMM1: D = X @ W1 (4 chunks, po=0) ----
    run_gemm<4>(g_wa, DN_, smb + K1_A, b0, 0, acc, tid, lane, m_base, n_base);

    // prefetch GEMM2 chunks 0..2 (po2 = 0) during the LayerNorm
    prologue_B(g_wb, DH_, b0, 0, tid);

    // ---- LN + ReLU -> A2 tiles (alias A1) ----
    ln_apply(acc, lng, lnb, sm + K1_A, ps, lane, m_base, n_base, warp_n);
    init_bias_reg(acc, b2, lane, n_base);

    // ---- GEMM2: D = H @ W2 (4 chunks, po=0) ----
    run_gemm<4>(g_wb, DH_, smb + K1_A, b0, 0, acc, tid, lane, m_base, n_base);

    // ---- epilogue: stage to smem, coalesced red4 scatter-add to g_agg ----
    __syncthreads();                 // all warps done reading A/B smem
    stage_acc(acc, stg, lane, m_base, n_base);
    __syncthreads();
    #pragma unroll 1
    for (int rr = 0; rr < 16; rr++) {
        int row = wid * 16 + rr;
        if (m0 + row < MM) {
            float* dst = &g_agg[(size_t)eid_s[row] * DH_];
            #pragma unroll
            for (int h = 0; h < 2; h++) {
                int col = h * 128 + lane * 4;
                float4 v = *(float4*)&stg[row * SP + col];
                red4(&dst[col], v.x, v.y, v.z, v.w);
            }
        }
    }
}

// =====================================================================
// Kernel 2: hyperedge -> node, GEMM1 K = 320
// =====================================================================
__global__ __launch_bounds__(256, 1)
void k_e2n(const int*   __restrict__ node_ids,
           const int*   __restrict__ he_ids,
           const float* __restrict__ he_attr,
           const float* __restrict__ he_count,
           const float* __restrict__ b1,
           const float* __restrict__ lng, const float* __restrict__ lnb,
           const float* __restrict__ b2)
{
    extern __shared__ char sm[];
    const uint32_t smb = s2u(sm);
    const int tid = threadIdx.x, wid = tid >> 5, lane = tid & 31;
    const int warp_m = wid >> 2, warp_n = wid & 3;
    const int m_base = warp_m * 64, n_base = warp_n * 64;
    const int m0 = blockIdx.x * MT;

    int* eid_s = (int*)(sm + K2_EID);
    int* nid_s = (int*)(sm + K2_NID);
    float* rc_s = (float*)(sm + K2_RC);
    float* ps  = (float*)(sm + K2_PS);
    float* stg = (float*)sm;
    const uint32_t b0 = smb + K2_B0;

    prologue_B(g_wc, DIN_, b0, 0, tid);

    if (tid < MT) {
        int m = m0 + tid;
        int mc = m < MM ? m : MM - 1;
        int e = he_ids[mc];
        eid_s[tid] = e;
        nid_s[tid] = node_ids[mc];
        rc_s[tid]  = 1.f / (__ldg(&he_count[e]) + 1e-6f);
    }
    __syncthreads();

    // gather [he_attr | agg/cnt] -> single fp16 swizzled A tiles (5 tiles)
    for (int i = tid; i < MT * 16; i += 256) {            // attr: k 0..63 (tile 0)
        int r = i >> 4, q = i & 15;
        float4 v = __ldg((const float4*)&he_attr[(size_t)eid_s[r] * DHA_ + q * 4]);
        u64 h = (u64)pkh(v.x, v.y) | ((u64)pkh(v.z, v.w) << 32);
        *(u64*)(sm + K2_A + SW128((uint32_t)(r * 128 + q * 8))) = h;
    }
    for (int i = tid; i < MT * 64; i += 256) {            // agg: k 64..319 (tiles 1-4)
        int r = i >> 6, c4 = i & 63;
        float rc = rc_s[r];
        float4 v = *(const float4*)&g_agg[(size_t)eid_s[r] * DH_ + c4 * 4];
        v.x *= rc; v.y *= rc; v.z *= rc; v.w *= rc;
        u64 h = (u64)pkh(v.x, v.y) | ((u64)pkh(v.z, v.w) << 32);
        int k = 64 + c4 * 4, tile = k >> 6, kin = k & 63;
        *(u64*)(sm + K2_A + tile * TILE_B + SW128((uint32_t)(r * 128 + kin * 2))) = h;
    }

    float acc[4][8][4];
    init_bias_reg(acc, b1, lane, n_base);

    // ---- GEMM1: D = [attr|agg] @ W1, K = 320 (5 chunks, po=0) ----
    run_gemm<5>(g_wc, DIN_, smb + K2_A, b0, 0, acc, tid, lane, m_base, n_base);

    // prefetch GEMM2 chunks 0..2 (po2 = (0+5)&3 = 1) during the LayerNorm
    prologue_B(g_wd, DH_, b0, 1, tid);

    // ---- LN + ReLU -> A2 tiles (alias A1 tiles 0-3) ----
    ln_apply(acc, lng, lnb, sm + K2_A, ps, lane, m_base, n_base, warp_n);
    init_bias_reg(acc, b2, lane, n_base);

    // ---- GEMM2: D = G @ W2, K = 256 (4 chunks, po=1) ----
    run_gemm<4>(g_wd, DH_, smb + K2_A, b0, 1, acc, tid, lane, m_base, n_base);

    // ---- epilogue: stage, coalesced relu+red4 scatter-add to g_acc + degree ----
    __syncthreads();
    stage_acc(acc, stg, lane, m_base, n_base);
    __syncthreads();
    #pragma unroll 1
    for (int rr = 0; rr < 16; rr++) {
        int row = wid * 16 + rr;
        if (m0 + row < MM) {
            int n = nid_s[row];
            float* dst = &g_acc[(size_t)n * DN_];
            #pragma unroll
            for (int h = 0; h < 2; h++) {
                int col = h * 128 + lane * 4;
                float4 v = *(float4*)&stg[row * SP + col];
                red4(&dst[col], fmaxf(v.x, 0.f), fmaxf(v.y, 0.f),
                                fmaxf(v.z, 0.f), fmaxf(v.w, 0.f));
            }
            if (lane == 0)
                asm volatile("red.global.add.f32 [%0], %1;" :: "l"(&g_deg[n]), "f"(1.f) : "memory");
        }
    }
}

// =====================================================================
// Kernel 3: out = x + LN(g_acc / (deg + eps)).  Warp per node row.
// =====================================================================
__global__ __launch_bounds__(256, 4)
void k_final(const float* __restrict__ x,
             const float* __restrict__ lng, const float* __restrict__ lnb,
             float* __restrict__ out)
{
    const int lane = threadIdx.x & 31;
    const int n = blockIdx.x * 8 + (threadIdx.x >> 5);
    if (n >= NN) return;

    float rd = 1.f / (g_deg[n] + 1e-6f);
    float v[8], s = 0.f, sq = 0.f;
    #pragma unroll
    for (int j = 0; j < 8; j++) {
        v[j] = g_acc[(size_t)n * DN_ + lane + j * 32] * rd;
        s += v[j]; sq += v[j] * v[j];
    }
    #pragma unroll
    for (int o = 16; o; o >>= 1) {
        s  += __shfl_xor_sync(0xffffffffu, s, o);
        sq += __shfl_xor_sync(0xffffffffu, sq, o);
    }
    float mu = s * (1.f / DN_);
    float var = sq * (1.f / DN_) - mu * mu;
    float rs = rsqrtf(var + 1e-5f);
    #pragma unroll
    for (int j = 0; j < 8; j++) {
        int c = lane + j * 32;
        float t = (v[j] - mu) * rs * __ldg(&lng[c]) + __ldg(&lnb[c]);
        out[(size_t)n * DN_ + c] = __ldg(&x[(size_t)n * DN_ + c]) + t;
    }
}

// =====================================================================
// launcher
// =====================================================================
extern "C" void kernel_launch(void* const* d_in, const int* in_sizes, int n_in,
                              void* d_out, int out_size)
{
    const float* x        = (const float*)d_in[0];
    const int*   node_ids = (const int*)  d_in[1];
    const int*   he_ids   = (const int*)  d_in[2];
    const float* he_attr  = (const float*)d_in[3];
    const float* he_count = (const float*)d_in[4];
    const float* n2e_w1   = (const float*)d_in[5];
    const float* n2e_b1   = (const float*)d_in[6];
    const float* n2e_lng  = (const float*)d_in[7];
    const float* n2e_lnb  = (const float*)d_in[8];
    const float* n2e_w2   = (const float*)d_in[9];
    const float* n2e_b2   = (const float*)d_in[10];
    const float* e2n_w1   = (const float*)d_in[11];
    const float* e2n_b1   = (const float*)d_in[12];
    const float* e2n_lng  = (const float*)d_in[13];
    const float* e2n_lnb  = (const float*)d_in[14];
    const float* e2n_w2   = (const float*)d_in[15];
    const float* e2n_b2   = (const float*)d_in[16];
    const float* ln_g     = (const float*)d_in[17];
    const float* ln_b     = (const float*)d_in[18];
    float* out = (float*)d_out;

    void *p_agg, *p_acc, *p_deg;
    cudaGetSymbolAddress(&p_agg, g_agg);
    cudaGetSymbolAddress(&p_acc, g_acc);
    cudaGetSymbolAddress(&p_deg, g_deg);
    cudaMemsetAsync(p_agg, 0, sizeof(float) * (size_t)EE * DH_);
    cudaMemsetAsync(p_acc, 0, sizeof(float) * (size_t)NN * DN_);
    cudaMemsetAsync(p_deg, 0, sizeof(float) * NN);

    k_prep_all<<<(PREP_TOTAL + 255) / 256, 256>>>(n2e_w1, n2e_w2, e2n_w1, e2n_w2);

    cudaFuncSetAttribute(k_n2e, cudaFuncAttributeMaxDynamicSharedMemorySize, K1_SMEM);
    cudaFuncSetAttribute(k_e2n, cudaFuncAttributeMaxDynamicSharedMemorySize, K2_SMEM);

    k_n2e<<<GRID1, 256, K1_SMEM>>>(x, node_ids, he_ids,
                                   n2e_b1, n2e_lng, n2e_lnb, n2e_b2);
    k_e2n<<<GRID1, 256, K2_SMEM>>>(node_ids, he_ids, he_attr, he_count,
                                   e2n_b1, e2n_lng, e2n_lnb, e2n_b2);
    k_final<<<(NN + 7) / 8, 256>>>(x, ln_g, ln_b, out);
}

// round 14
// speedup vs baseline: 2.9674x; 1.2789x over previous
#include <cuda_runtime.h>
#include <cuda_fp16.h>
#include <cstdint>

// ---------------- problem constants ----------------
#define NN   50000
#define MM   200000
#define EE   10000
#define DN_  256
#define DHA_ 64
#define DH_  256
#define DIN_ 320

#define MT   64           // rows per block (2 CTAs/SM)
#define KC   64           // K chunk (one SW128 tile)
#define TILE_B (MT * 128) // bytes of one [64][64] fp16 tile = 8192
#define BCH  32768        // bytes of one B chunk [256][64] fp16
#define SP   264          // stage pitch in floats

#define GRID1 (MM / MT)   // 3125 (exact)

typedef unsigned long long u64;

// ---------------- device scratch ----------------
__device__ float g_agg[(size_t)EE * DH_];
__device__ float g_acc[(size_t)NN * DN_];
__device__ float g_deg[NN];

// transposed fp16 weights: [N][K]
__device__ __half g_wa[DN_ * DH_];    // n2e_w1^T [256][256]
__device__ __half g_wb[DH_ * DH_];    // n2e_w2^T [256][256]
__device__ __half g_wc[DH_ * DIN_];   // e2n_w1^T [256][320]
__device__ __half g_wd[DN_ * DH_];    // e2n_w2^T [256][256]

// ---------------- helpers ----------------
__device__ __forceinline__ uint32_t s2u(const void* p) {
    uint32_t a;
    asm("{ .reg .u64 t; cvta.to.shared.u64 t, %1; cvt.u32.u64 %0, t; }" : "=r"(a) : "l"(p));
    return a;
}
#define SW128(x) ((x) ^ ((((x) >> 3) & 0x70)))

__device__ __forceinline__ void ldsm4(uint32_t* r, uint32_t a) {
    asm volatile("ldmatrix.sync.aligned.m8n8.x4.shared.b16 {%0,%1,%2,%3}, [%4];"
        : "=r"(r[0]), "=r"(r[1]), "=r"(r[2]), "=r"(r[3]) : "r"(a));
}
__device__ __forceinline__ void mma16816h(float* d, const uint32_t* a, const uint32_t* b) {
    asm volatile("mma.sync.aligned.m16n8k16.row.col.f32.f16.f16.f32 "
        "{%0,%1,%2,%3}, {%4,%5,%6,%7}, {%8,%9}, {%0,%1,%2,%3};"
        : "+f"(d[0]), "+f"(d[1]), "+f"(d[2]), "+f"(d[3])
        : "r"(a[0]), "r"(a[1]), "r"(a[2]), "r"(a[3]), "r"(b[0]), "r"(b[1]));
}
__device__ __forceinline__ void red4(float* p, float a, float b, float c, float d) {
    asm volatile("red.global.add.v4.f32 [%0], {%1, %2, %3, %4};"
                 :: "l"(p), "f"(a), "f"(b), "f"(c), "f"(d) : "memory");
}
__device__ __forceinline__ void cpa16(uint32_t dst, const void* src) {
    asm volatile("cp.async.cg.shared.global [%0], [%1], 16;" :: "r"(dst), "l"(src) : "memory");
}
#define CP_COMMIT() asm volatile("cp.async.commit_group;" ::: "memory")
#define CP_WAIT1()  asm volatile("cp.async.wait_group 1;" ::: "memory")

// pack 2 floats -> fp16x2 (first arg -> low half / lower address)
__device__ __forceinline__ uint32_t pkh(float lo, float hi) {
    __half2 h = __floats2half2_rn(lo, hi);
    return *reinterpret_cast<uint32_t*>(&h);
}

// ---------------- B chunk load: [256 n][64 k] fp16, coalesced cp.async ----------------
__device__ __forceinline__ void load_B_chunk(const __half* __restrict__ w,
                                             int kc, int kstride,
                                             uint32_t bB, int tid)
{
    #pragma unroll
    for (int it = 0; it < 8; it++) {
        int i = it * 256 + tid;
        int n = i >> 3, q = i & 7;
        size_t src = (size_t)n * kstride + kc * KC + q * 8;
        cpa16(bB + SW128((uint32_t)(n * 128 + q * 16)), w + src);
    }
}

// ---------------- MMA for one k64 chunk (warp tile 32x64) ----------------
__device__ __forceinline__ void gemm_chunk(uint32_t aT, uint32_t bB,
                                           float (*acc)[8][4],
                                           int lane, int m_base, int n_base)
{
    const uint32_t swz  = (uint32_t)(lane & 7) << 4;
    const uint32_t arow = (uint32_t)(m_base + (lane & 15)) * 128;
    const uint32_t aka  = (uint32_t)((lane >> 4) << 3) * 2;
    const uint32_t brow = (uint32_t)(n_base + ((lane >> 4) << 3) + (lane & 7)) * 128;
    const uint32_t bka  = (uint32_t)(((lane >> 3) & 1) << 3) * 2;

    #pragma unroll
    for (int ks = 0; ks < 4; ks++) {
        const uint32_t koff = (uint32_t)ks * 32;
        const uint32_t aoff = arow + ((koff + aka) ^ swz);
        const uint32_t boff = brow + ((koff + bka) ^ swz);
        uint32_t fa[2][4], fb[4][4];
        #pragma unroll
        for (int mi = 0; mi < 2; mi++) ldsm4(fa[mi], aT + aoff + mi * 2048);
        #pragma unroll
        for (int j = 0; j < 4; j++)  ldsm4(fb[j], bB + boff + j * 2048);
        #pragma unroll
        for (int mi = 0; mi < 2; mi++)
            #pragma unroll
            for (int j = 0; j < 4; j++) {
                mma16816h(acc[mi][2 * j],     fa[mi], fb[j]);
                mma16816h(acc[mi][2 * j + 1], fa[mi], fb[j] + 2);
            }
    }
}

// 2-deep-ring pipelined GEMM over C k64 chunks.
// buf(c) = b0 + ((po + c) & 1) * BCH.  Prologue: chunk 0 committed into buf(po).
template<int C>
__device__ __forceinline__ void run_gemm(const __half* __restrict__ w, int kstride,
                                         uint32_t aBase, uint32_t b0, int po,
                                         float (*acc)[8][4],
                                         int tid, int lane, int m_base, int n_base)
{
    #pragma unroll 1
    for (int c = 0; c < C; c++) {
        if (c + 1 < C)
            load_B_chunk(w, c + 1, kstride, b0 + (uint32_t)((po + c + 1) & 1) * BCH, tid);
        CP_COMMIT();
        CP_WAIT1();
        __syncthreads();
        gemm_chunk(aBase + c * TILE_B, b0 + (uint32_t)((po + c) & 1) * BCH,
                   acc, lane, m_base, n_base);
        __syncthreads();
    }
}

// prologue: issue chunk 0 into buf(po), one commit group
__device__ __forceinline__ void prologue_B(const __half* __restrict__ w, int kstride,
                                           uint32_t b0, int po, int tid)
{
    load_B_chunk(w, 0, kstride, b0 + (uint32_t)(po & 1) * BCH, tid);
    CP_COMMIT();
}

__device__ __forceinline__ void init_bias_reg(float (*acc)[8][4],
                                              const float* __restrict__ b,
                                              int lane, int n_base)
{
    #pragma unroll
    for (int ni = 0; ni < 8; ni++) {
        int c = n_base + ni * 8 + 2 * (lane & 3);
        float v0 = __ldg(&b[c]), v1 = __ldg(&b[c + 1]);
        #pragma unroll
        for (int mi = 0; mi < 2; mi++) {
            acc[mi][ni][0] = v0; acc[mi][ni][1] = v1;
            acc[mi][ni][2] = v0; acc[mi][ni][3] = v1;
        }
    }
}

// LayerNorm + ReLU on register accumulators -> single fp16 A2 smem tiles.
__device__ __forceinline__ void ln_apply(float (*acc)[8][4],
                                         const float* __restrict__ lng,
                                         const float* __restrict__ lnb,
                                         char* a2, float* ps,
                                         int lane, int m_base, int n_base, int warp_n)
{
    #pragma unroll
    for (int mi = 0; mi < 2; mi++) {
        float sl = 0.f, ql = 0.f, sh = 0.f, qh = 0.f;
        #pragma unroll
        for (int ni = 0; ni < 8; ni++) {
            float a0 = acc[mi][ni][0], a1 = acc[mi][ni][1];
            float a2v = acc[mi][ni][2], a3 = acc[mi][ni][3];
            sl += a0 + a1; ql += a0 * a0 + a1 * a1;
            sh += a2v + a3; qh += a2v * a2v + a3 * a3;
        }
        sl += __shfl_xor_sync(0xffffffffu, sl, 1); sl += __shfl_xor_sync(0xffffffffu, sl, 2);
        ql += __shfl_xor_sync(0xffffffffu, ql, 1); ql += __shfl_xor_sync(0xffffffffu, ql, 2);
        sh += __shfl_xor_sync(0xffffffffu, sh, 1); sh += __shfl_xor_sync(0xffffffffu, sh, 2);
        qh += __shfl_xor_sync(0xffffffffu, qh, 1); qh += __shfl_xor_sync(0xffffffffu, qh, 2);
        if ((lane & 3) == 0) {
            int rl = m_base + mi * 16 + (lane >> 2);
            ps[rl * 4 + warp_n] = sl;        ps[256 + rl * 4 + warp_n] = ql;
            ps[(rl + 8) * 4 + warp_n] = sh;  ps[256 + (rl + 8) * 4 + warp_n] = qh;
        }
    }
    __syncthreads();
    float mu[2][2], rsd[2][2];
    #pragma unroll
    for (int mi = 0; mi < 2; mi++) {
        int rl = m_base + mi * 16 + (lane >> 2);
        #pragma unroll
        for (int h = 0; h < 2; h++) {
            int r = rl + h * 8;
            float s = ps[r * 4] + ps[r * 4 + 1] + ps[r * 4 + 2] + ps[r * 4 + 3];
            float q = ps[256 + r * 4] + ps[256 + r * 4 + 1] + ps[256 + r * 4 + 2] + ps[256 + r * 4 + 3];
            float m = s * (1.f / 256.f);
            float var = q * (1.f / 256.f) - m * m;
            mu[mi][h] = m;
            rsd[mi][h] = rsqrtf(var + 1e-5f);
        }
    }
    __syncthreads();
    #pragma unroll
    for (int mi = 0; mi < 2; mi++) {
        int rl = m_base + mi * 16 + (lane >> 2);
        int rh = rl + 8;
        uint32_t rswz = (uint32_t)(lane >> 2) << 4;
        #pragma unroll
        for (int ni = 0; ni < 8; ni++) {
            int cl = ni * 8 + 2 * (lane & 3);
            int c  = n_base + cl;
            float g0 = __ldg(&lng[c]),  g1 = __ldg(&lng[c + 1]);
            float B0 = __ldg(&lnb[c]),  B1 = __ldg(&lnb[c + 1]);
            uint32_t kb = ((uint32_t)(cl * 2)) ^ rswz;
            {
                float t0 = fmaxf((acc[mi][ni][0] - mu[mi][0]) * rsd[mi][0] * g0 + B0, 0.f);
                float t1 = fmaxf((acc[mi][ni][1] - mu[mi][0]) * rsd[mi][0] * g1 + B1, 0.f);
                *(uint32_t*)(a2 + (uint32_t)warp_n * TILE_B + (uint32_t)rl * 128 + kb) = pkh(t0, t1);
            }
            {
                float t0 = fmaxf((acc[mi][ni][2] - mu[mi][1]) * rsd[mi][1] * g0 + B0, 0.f);
                float t1 = fmaxf((acc[mi][ni][3] - mu[mi][1]) * rsd[mi][1] * g1 + B1, 0.f);
                *(uint32_t*)(a2 + (uint32_t)warp_n * TILE_B + (uint32_t)rh * 128 + kb) = pkh(t0, t1);
            }
        }
    }
}

// stage acc (bias already included) into fp32 smem tile [64][SP]
__device__ __forceinline__ void stage_acc(float (*acc)[8][4], float* stg,
                                          int lane, int m_base, int n_base)
{
    #pragma unroll
    for (int mi = 0; mi < 2; mi++) {
        int rl = m_base + mi * 16 + (lane >> 2);
        int rh = rl + 8;
        #pragma unroll
        for (int ni = 0; ni < 8; ni++) {
            int col = n_base + ni * 8 + 2 * (lane & 3);
            *(float2*)&stg[rl * SP + col] = make_float2(acc[mi][ni][0], acc[mi][ni][1]);
            *(float2*)&stg[rh * SP + col] = make_float2(acc[mi][ni][2], acc[mi][ni][3]);
        }
    }
}

// ---------------- prep: all 4 weights -> transposed fp16 [N][K] ----------------
#define PREP_TOTAL (65536 + 65536 + 81920 + 65536)
__global__ void k_prep_all(const float* __restrict__ wa, const float* __restrict__ wb,
                           const float* __restrict__ wc, const float* __restrict__ wd)
{
    int i = blockIdx.x * 256 + threadIdx.x;
    if (i >= PREP_TOTAL) return;
    const float* w; __half* th; int K, N, j;
    if (i < 65536)       { w = wa; th = g_wa; K = 256; N = 256; j = i; }
    else if (i < 131072) { w = wb; th = g_wb; K = 256; N = 256; j = i - 65536; }
    else if (i < 212992) { w = wc; th = g_wc; K = 320; N = 256; j = i - 131072; }
    else                 { w = wd; th = g_wd; K = 256; N = 256; j = i - 212992; }
    int n = j / K, k = j - n * K;
    th[j] = __float2half(__ldg(&w[(size_t)k * N + n]));
}

// ---------------- smem offsets ----------------
// K1: A 4 tiles (32K) @0, B ring 2x32K @32768, ps 2K @98304, ids @100352
#define K1_A   0
#define K1_B0  32768
#define K1_PS  98304
#define K1_EID 100352
#define K1_NID 100608
#define K1_SMEM 100864

// K2: A 5 tiles (40K) @0, B ring 2x32K @40960, ps 2K @106496, ids @108544
#define K2_A   0
#define K2_B0  40960
#define K2_PS  106496
#define K2_EID 108544
#define K2_NID 108800
#define K2_RC  109056
#define K2_SMEM 109312

// =====================================================================
// Kernel 1: node -> hyperedge
// =====================================================================
__global__ __launch_bounds__(256, 2)
void k_n2e(const float* __restrict__ x,
           const int*   __restrict__ node_ids,
           const int*   __restrict__ he_ids,
           const float* __restrict__ b1,
           const float* __restrict__ lng, const float* __restrict__ lnb,
           const float* __restrict__ b2)
{
    extern __shared__ char sm[];
    const uint32_t smb = s2u(sm);
    const int tid = threadIdx.x, wid = tid >> 5, lane = tid & 31;
    const int warp_m = wid >> 2, warp_n = wid & 3;
    const int m_base = warp_m * 32, n_base = warp_n * 64;
    const int m0 = blockIdx.x * MT;

    int* eid_s = (int*)(sm + K1_EID);
    int* nid_s = (int*)(sm + K1_NID);
    float* ps  = (float*)(sm + K1_PS);
    float* stg = (float*)sm;
    const uint32_t b0 = smb + K1_B0;

    prologue_B(g_wa, DN_, b0, 0, tid);

    if (tid < MT) {
        int m = m0 + tid;
        eid_s[tid] = he_ids[m];
        nid_s[tid] = node_ids[m];
    }
    __syncthreads();

    // gather x -> single fp16 swizzled A tiles
    for (int i = tid; i < MT * 64; i += 256) {
        int r = i >> 6, c4 = i & 63;
        float4 v = __ldg((const float4*)&x[(size_t)nid_s[r] * DN_ + c4 * 4]);
        u64 h = (u64)pkh(v.x, v.y) | ((u64)pkh(v.z, v.w) << 32);
        int k = c4 * 4, tile = k >> 6, kin = k & 63;
        *(u64*)(sm + K1_A + tile * TILE_B + SW128((uint32_t)(r * 128 + kin * 2))) = h;
    }

    float acc[2][8][4];
    init_bias_reg(acc, b1, lane, n_base);

    // ---- GEMM1: D = X @ W1 (4 chunks, po=0) ----
    run_gemm<4>(g_wa, DN_, smb + K1_A, b0, 0, acc, tid, lane, m_base, n_base);

    // prefetch GEMM2 chunk 0 (po2 = (0+4)&1 = 0) during the LayerNorm
    prologue_B(g_wb, DH_, b0, 0, tid);

    // ---- LN + ReLU -> A2 tiles (alias A1) ----
    ln_apply(acc, lng, lnb, sm + K1_A, ps, lane, m_base, n_base, warp_n);
    init_bias_reg(acc, b2, lane, n_base);

    // ---- GEMM2: D = H @ W2 (4 chunks, po=0) ----
    run_gemm<4>(g_wb, DH_, smb + K1_A, b0, 0, acc, tid, lane, m_base, n_base);

    // ---- epilogue: stage to smem, coalesced red4 scatter-add to g_agg ----
    stage_acc(acc, stg, lane, m_base, n_base);
    __syncthreads();
    #pragma unroll 1
    for (int rr = 0; rr < 8; rr++) {
        int row = wid * 8 + rr;
        if (m0 + row < MM) {
            float* dst = &g_agg[(size_t)eid_s[row] * DH_];
            #pragma unroll
            for (int h = 0; h < 2; h++) {
                int col = h * 128 + lane * 4;
                float4 v = *(float4*)&stg[row * SP + col];
                red4(&dst[col], v.x, v.y, v.z, v.w);
            }
        }
    }
}

// =====================================================================
// Kernel 2: hyperedge -> node, GEMM1 K = 320
// =====================================================================
__global__ __launch_bounds__(256, 2)
void k_e2n(const int*   __restrict__ node_ids,
           const int*   __restrict__ he_ids,
           const float* __restrict__ he_attr,
           const float* __restrict__ he_count,
           const float* __restrict__ b1,
           const float* __restrict__ lng, const float* __restrict__ lnb,
           const float* __restrict__ b2)
{
    extern __shared__ char sm[];
    const uint32_t smb = s2u(sm);
    const int tid = threadIdx.x, wid = tid >> 5, lane = tid & 31;
    const int warp_m = wid >> 2, warp_n = wid & 3;
    const int m_base = warp_m * 32, n_base = warp_n * 64;
    const int m0 = blockIdx.x * MT;

    int* eid_s = (int*)(sm + K2_EID);
    int* nid_s = (int*)(sm + K2_NID);
    float* rc_s = (float*)(sm + K2_RC);
    float* ps  = (float*)(sm + K2_PS);
    float* stg = (float*)sm;
    const uint32_t b0 = smb + K2_B0;

    prologue_B(g_wc, DIN_, b0, 0, tid);

    if (tid < MT) {
        int m = m0 + tid;
        int e = he_ids[m];
        eid_s[tid] = e;
        nid_s[tid] = node_ids[m];
        rc_s[tid]  = 1.f / (__ldg(&he_count[e]) + 1e-6f);
    }
    __syncthreads();

    // gather [he_attr | agg/cnt] -> single fp16 swizzled A tiles (5 tiles)
    for (int i = tid; i < MT * 16; i += 256) {            // attr: k 0..63 (tile 0)
        int r = i >> 4, q = i & 15;
        float4 v = __ldg((const float4*)&he_attr[(size_t)eid_s[r] * DHA_ + q * 4]);
        u64 h = (u64)pkh(v.x, v.y) | ((u64)pkh(v.z, v.w) << 32);
        *(u64*)(sm + K2_A + SW128((uint32_t)(r * 128 + q * 8))) = h;
    }
    for (int i = tid; i < MT * 64; i += 256) {            // agg: k 64..319 (tiles 1-4)
        int r = i >> 6, c4 = i & 63;
        float rc = rc_s[r];
        float4 v = *(const float4*)&g_agg[(size_t)eid_s[r] * DH_ + c4 * 4];
        v.x *= rc; v.y *= rc; v.z *= rc; v.w *= rc;
        u64 h = (u64)pkh(v.x, v.y) | ((u64)pkh(v.z, v.w) << 32);
        int k = 64 + c4 * 4, tile = k >> 6, kin = k & 63;
        *(u64*)(sm + K2_A + tile * TILE_B + SW128((uint32_t)(r * 128 + kin * 2))) = h;
    }

    float acc[2][8][4];
    init_bias_reg(acc, b1, lane, n_base);

    // ---- GEMM1: D = [attr|agg] @ W1, K = 320 (5 chunks, po=0) ----
    run_gemm<5>(g_wc, DIN_, smb + K2_A, b0, 0, acc, tid, lane, m_base, n_base);

    // prefetch GEMM2 chunk 0 (po2 = (0+5)&1 = 1) during the LayerNorm
    prologue_B(g_wd, DH_, b0, 1, tid);

    // ---- LN + ReLU -> A2 tiles (alias A1 tiles 0-3) ----
    ln_apply(acc, lng, lnb, sm + K2_A, ps, lane, m_base, n_base, warp_n);
    init_bias_reg(acc, b2, lane, n_base);

    // ---- GEMM2: D = G @ W2, K = 256 (4 chunks, po=1) ----
    run_gemm<4>(g_wd, DH_, smb + K2_A, b0, 1, acc, tid, lane, m_base, n_base);

    // ---- epilogue: stage, coalesced relu+red4 scatter-add to g_acc + degree ----
    stage_acc(acc, stg, lane, m_base, n_base);
    __syncthreads();
    #pragma unroll 1
    for (int rr = 0; rr < 8; rr++) {
        int row = wid * 8 + rr;
        if (m0 + row < MM) {
            int n = nid_s[row];
            float* dst = &g_acc[(size_t)n * DN_];
            #pragma unroll
            for (int h = 0; h < 2; h++) {
                int col = h * 128 + lane * 4;
                float4 v = *(float4*)&stg[row * SP + col];
                red4(&dst[col], fmaxf(v.x, 0.f), fmaxf(v.y, 0.f),
                                fmaxf(v.z, 0.f), fmaxf(v.w, 0.f));
            }
            if (lane == 0)
                asm volatile("red.global.add.f32 [%0], %1;" :: "l"(&g_deg[n]), "f"(1.f) : "memory");
        }
    }
}

// =====================================================================
// Kernel 3: out = x + LN(g_acc / (deg + eps)).  Warp per node row.
// =====================================================================
__global__ __launch_bounds__(256, 4)
void k_final(const float* __restrict__ x,
             const float* __restrict__ lng, const float* __restrict__ lnb,
             float* __restrict__ out)
{
    const int lane = threadIdx.x & 31;
    const int n = blockIdx.x * 8 + (threadIdx.x >> 5);
    if (n >= NN) return;

    float rd = 1.f / (g_deg[n] + 1e-6f);
    float v[8], s = 0.f, sq = 0.f;
    #pragma unroll
    for (int j = 0; j < 8; j++) {
        v[j] = g_acc[(size_t)n * DN_ + lane + j * 32] * rd;
        s += v[j]; sq += v[j] * v[j];
    }
    #pragma unroll
    for (int o = 16; o; o >>= 1) {
        s  += __shfl_xor_sync(0xffffffffu, s, o);
        sq += __shfl_xor_sync(0xffffffffu, sq, o);
    }
    float mu = s * (1.f / DN_);
    float var = sq * (1.f / DN_) - mu * mu;
    float rs = rsqrtf(var + 1e-5f);
    #pragma unroll
    for (int j = 0; j < 8; j++) {
        int c = lane + j * 32;
        float t = (v[j] - mu) * rs * __ldg(&lng[c]) + __ldg(&lnb[c]);
        out[(size_t)n * DN_ + c] = __ldg(&x[(size_t)n * DN_ + c]) + t;
    }
}

// =====================================================================
// launcher
// =====================================================================
extern "C" void kernel_launch(void* const* d_in, const int* in_sizes, int n_in,
                              void* d_out, int out_size)
{
    const float* x        = (const float*)d_in[0];
    const int*   node_ids = (const int*)  d_in[1];
    const int*   he_ids   = (const int*)  d_in[2];
    const float* he_attr  = (const float*)d_in[3];
    const float* he_count = (const float*)d_in[4];
    const float* n2e_w1   = (const float*)d_in[5];
    const float* n2e_b1   = (const float*)d_in[6];
    const float* n2e_lng  = (const float*)d_in[7];
    const float* n2e_lnb  = (const float*)d_in[8];
    const float* n2e_w2   = (const float*)d_in[9];
    const float* n2e_b2   = (const float*)d_in[10];
    const float* e2n_w1   = (const float*)d_in[11];
    const float* e2n_b1   = (const float*)d_in[12];
    const float* e2n_lng  = (const float*)d_in[13];
    const float* e2n_lnb  = (const float*)d_in[14];
    const float* e2n_w2   = (const float*)d_in[15];
    const float* e2n_b2   = (const float*)d_in[16];
    const float* ln_g     = (const float*)d_in[17];
    const float* ln_b     = (const float*)d_in[18];
    float* out = (float*)d_out;

    void *p_agg, *p_acc, *p_deg;
    cudaGetSymbolAddress(&p_agg, g_agg);
    cudaGetSymbolAddress(&p_acc, g_acc);
    cudaGetSymbolAddress(&p_deg, g_deg);
    cudaMemsetAsync(p_agg, 0, sizeof(float) * (size_t)EE * DH_);
    cudaMemsetAsync(p_acc, 0, sizeof(float) * (size_t)NN * DN_);
    cudaMemsetAsync(p_deg, 0, sizeof(float) * NN);

    k_prep_all<<<(PREP_TOTAL + 255) / 256, 256>>>(n2e_w1, n2e_w2, e2n_w1, e2n_w2);

    cudaFuncSetAttribute(k_n2e, cudaFuncAttributeMaxDynamicSharedMemorySize, K1_SMEM);
    cudaFuncSetAttribute(k_e2n, cudaFuncAttributeMaxDynamicSharedMemorySize, K2_SMEM);

    k_n2e<<<GRID1, 256, K1_SMEM>>>(x, node_ids, he_ids,
                                   n2e_b1, n2e_lng, n2e_lnb, n2e_b2);
    k_e2n<<<GRID1, 256, K2_SMEM>>>(node_ids, he_ids, he_attr, he_count,
                                   e2n_b1, e2n_lng, e2n_lnb, e2n_b2);
    k_final<<<(NN + 7) / 8, 256>>>(x, ln_g, ln_b, out);
}

// round 16
// speedup vs baseline: 2.9968x; 1.0099x over previous
#include <cuda_runtime.h>
#include <cuda_fp16.h>
#include <cstdint>

// ---------------- problem constants ----------------
#define NN   50000
#define MM   200000
#define EE   10000
#define DN_  256
#define DHA_ 64
#define DH_  256
#define DIN_ 320

#define MT   64           // rows per block (2 CTAs/SM)
#define KC   64           // K chunk (one SW128 tile)
#define TILE_B (MT * 128) // bytes of one [64][64] fp16 tile = 8192
#define BCH  32768        // bytes of one B chunk [256][64] fp16
#define SP   264          // stage pitch in floats

#define GRID1 (MM / MT)   // 3125 (exact)

typedef unsigned long long u64;

// ---------------- device scratch ----------------
__device__ float g_agg[(size_t)EE * DH_];
__device__ float g_acc[(size_t)NN * DN_];
__device__ float g_deg[NN];

// transposed fp16 weights: [N][K]
__device__ __half g_wa[DN_ * DH_];    // n2e_w1^T [256][256]
__device__ __half g_wb[DH_ * DH_];    // n2e_w2^T [256][256]
__device__ __half g_wc[DH_ * DIN_];   // e2n_w1^T [256][320]
__device__ __half g_wd[DN_ * DH_];    // e2n_w2^T [256][256]

// ---------------- helpers ----------------
__device__ __forceinline__ uint32_t s2u(const void* p) {
    uint32_t a;
    asm("{ .reg .u64 t; cvta.to.shared.u64 t, %1; cvt.u32.u64 %0, t; }" : "=r"(a) : "l"(p));
    return a;
}
#define SW128(x) ((x) ^ ((((x) >> 3) & 0x70)))

__device__ __forceinline__ void ldsm4(uint32_t* r, uint32_t a) {
    asm volatile("ldmatrix.sync.aligned.m8n8.x4.shared.b16 {%0,%1,%2,%3}, [%4];"
        : "=r"(r[0]), "=r"(r[1]), "=r"(r[2]), "=r"(r[3]) : "r"(a));
}
__device__ __forceinline__ void mma16816h(float* d, const uint32_t* a, const uint32_t* b) {
    asm volatile("mma.sync.aligned.m16n8k16.row.col.f32.f16.f16.f32 "
        "{%0,%1,%2,%3}, {%4,%5,%6,%7}, {%8,%9}, {%0,%1,%2,%3};"
        : "+f"(d[0]), "+f"(d[1]), "+f"(d[2]), "+f"(d[3])
        : "r"(a[0]), "r"(a[1]), "r"(a[2]), "r"(a[3]), "r"(b[0]), "r"(b[1]));
}
__device__ __forceinline__ void red4(float* p, float a, float b, float c, float d) {
    asm volatile("red.global.add.v4.f32 [%0], {%1, %2, %3, %4};"
                 :: "l"(p), "f"(a), "f"(b), "f"(c), "f"(d) : "memory");
}
__device__ __forceinline__ void cpa16(uint32_t dst, const void* src) {
    asm volatile("cp.async.cg.shared.global [%0], [%1], 16;" :: "r"(dst), "l"(src) : "memory");
}
#define CP_COMMIT() asm volatile("cp.async.commit_group;" ::: "memory")
#define CP_WAIT1()  asm volatile("cp.async.wait_group 1;" ::: "memory")

// pack 2 floats -> fp16x2 (first arg -> low half / lower address)
__device__ __forceinline__ uint32_t pkh(float lo, float hi) {
    __half2 h = __floats2half2_rn(lo, hi);
    return *reinterpret_cast<uint32_t*>(&h);
}

// ---------------- B chunk load: [256 n][64 k] fp16, coalesced cp.async ----------------
__device__ __forceinline__ void load_B_chunk(const __half* __restrict__ w,
                                             int kc, int kstride,
                                             uint32_t bB, int tid)
{
    #pragma unroll
    for (int it = 0; it < 8; it++) {
        int i = it * 256 + tid;
        int n = i >> 3, q = i & 7;
        size_t src = (size_t)n * kstride + kc * KC + q * 8;
        cpa16(bB + SW128((uint32_t)(n * 128 + q * 16)), w + src);
    }
}

// ---------------- MMA for one k64 chunk (warp tile 32x64) ----------------
__device__ __forceinline__ void gemm_chunk(uint32_t aT, uint32_t bB,
                                           float (*acc)[8][4],
                                           int lane, int m_base, int n_base)
{
    const uint32_t swz  = (uint32_t)(lane & 7) << 4;
    const uint32_t arow = (uint32_t)(m_base + (lane & 15)) * 128;
    const uint32_t aka  = (uint32_t)((lane >> 4) << 3) * 2;
    const uint32_t brow = (uint32_t)(n_base + ((lane >> 4) << 3) + (lane & 7)) * 128;
    const uint32_t bka  = (uint32_t)(((lane >> 3) & 1) << 3) * 2;

    #pragma unroll
    for (int ks = 0; ks < 4; ks++) {
        const uint32_t koff = (uint32_t)ks * 32;
        const uint32_t aoff = arow + ((koff + aka) ^ swz);
        const uint32_t boff = brow + ((koff + bka) ^ swz);
        uint32_t fa[2][4], fb[4][4];
        #pragma unroll
        for (int mi = 0; mi < 2; mi++) ldsm4(fa[mi], aT + aoff + mi * 2048);
        #pragma unroll
        for (int j = 0; j < 4; j++)  ldsm4(fb[j], bB + boff + j * 2048);
        #pragma unroll
        for (int mi = 0; mi < 2; mi++)
            #pragma unroll
            for (int j = 0; j < 4; j++) {
                mma16816h(acc[mi][2 * j],     fa[mi], fb[j]);
                mma16816h(acc[mi][2 * j + 1], fa[mi], fb[j] + 2);
            }
    }
}

// 2-deep-ring pipelined GEMM over C k64 chunks.
// buf(c) = b0 + ((po + c) & 1) * BCH.  Prologue: chunk 0 committed into buf(po).
template<int C>
__device__ __forceinline__ void run_gemm(const __half* __restrict__ w, int kstride,
                                         uint32_t aBase, uint32_t b0, int po,
                                         float (*acc)[8][4],
                                         int tid, int lane, int m_base, int n_base)
{
    #pragma unroll 1
    for (int c = 0; c < C; c++) {
        if (c + 1 < C)
            load_B_chunk(w, c + 1, kstride, b0 + (uint32_t)((po + c + 1) & 1) * BCH, tid);
        CP_COMMIT();
        CP_WAIT1();
        __syncthreads();
        gemm_chunk(aBase + c * TILE_B, b0 + (uint32_t)((po + c) & 1) * BCH,
                   acc, lane, m_base, n_base);
        __syncthreads();
    }
}

// prologue: issue chunk 0 into buf(po), one commit group
__device__ __forceinline__ void prologue_B(const __half* __restrict__ w, int kstride,
                                           uint32_t b0, int po, int tid)
{
    load_B_chunk(w, 0, kstride, b0 + (uint32_t)(po & 1) * BCH, tid);
    CP_COMMIT();
}

__device__ __forceinline__ void init_bias_reg(float (*acc)[8][4],
                                              const float* __restrict__ b,
                                              int lane, int n_base)
{
    #pragma unroll
    for (int ni = 0; ni < 8; ni++) {
        int c = n_base + ni * 8 + 2 * (lane & 3);
        float v0 = __ldg(&b[c]), v1 = __ldg(&b[c + 1]);
        #pragma unroll
        for (int mi = 0; mi < 2; mi++) {
            acc[mi][ni][0] = v0; acc[mi][ni][1] = v1;
            acc[mi][ni][2] = v0; acc[mi][ni][3] = v1;
        }
    }
}

// LayerNorm + ReLU on register accumulators -> single fp16 A2 smem tiles.
__device__ __forceinline__ void ln_apply(float (*acc)[8][4],
                                         const float* __restrict__ lng,
                                         const float* __restrict__ lnb,
                                         char* a2, float* ps,
                                         int lane, int m_base, int n_base, int warp_n)
{
    #pragma unroll
    for (int mi = 0; mi < 2; mi++) {
        float sl = 0.f, ql = 0.f, sh = 0.f, qh = 0.f;
        #pragma unroll
        for (int ni = 0; ni < 8; ni++) {
            float a0 = acc[mi][ni][0], a1 = acc[mi][ni][1];
            float a2v = acc[mi][ni][2], a3 = acc[mi][ni][3];
            sl += a0 + a1; ql += a0 * a0 + a1 * a1;
            sh += a2v + a3; qh += a2v * a2v + a3 * a3;
        }
        sl += __shfl_xor_sync(0xffffffffu, sl, 1); sl += __shfl_xor_sync(0xffffffffu, sl, 2);
        ql += __shfl_xor_sync(0xffffffffu, ql, 1); ql += __shfl_xor_sync(0xffffffffu, ql, 2);
        sh += __shfl_xor_sync(0xffffffffu, sh, 1); sh += __shfl_xor_sync(0xffffffffu, sh, 2);
        qh += __shfl_xor_sync(0xffffffffu, qh, 1); qh += __shfl_xor_sync(0xffffffffu, qh, 2);
        if ((lane & 3) == 0) {
            int rl = m_base + mi * 16 + (lane >> 2);
            ps[rl * 4 + warp_n] = sl;        ps[256 + rl * 4 + warp_n] = ql;
            ps[(rl + 8) * 4 + warp_n] = sh;  ps[256 + (rl + 8) * 4 + warp_n] = qh;
        }
    }
    __syncthreads();
    float mu[2][2], rsd[2][2];
    #pragma unroll
    for (int mi = 0; mi < 2; mi++) {
        int rl = m_base + mi * 16 + (lane >> 2);
        #pragma unroll
        for (int h = 0; h < 2; h++) {
            int r = rl + h * 8;
            float s = ps[r * 4] + ps[r * 4 + 1] + ps[r * 4 + 2] + ps[r * 4 + 3];
            float q = ps[256 + r * 4] + ps[256 + r * 4 + 1] + ps[256 + r * 4 + 2] + ps[256 + r * 4 + 3];
            float m = s * (1.f / 256.f);
            float var = q * (1.f / 256.f) - m * m;
            mu[mi][h] = m;
            rsd[mi][h] = rsqrtf(var + 1e-5f);
        }
    }
    __syncthreads();
    #pragma unroll
    for (int mi = 0; mi < 2; mi++) {
        int rl = m_base + mi * 16 + (lane >> 2);
        int rh = rl + 8;
        uint32_t rswz = (uint32_t)(lane >> 2) << 4;
        #pragma unroll
        for (int ni = 0; ni < 8; ni++) {
            int cl = ni * 8 + 2 * (lane & 3);
            int c  = n_base + cl;
            float g0 = __ldg(&lng[c]),  g1 = __ldg(&lng[c + 1]);
            float B0 = __ldg(&lnb[c]),  B1 = __ldg(&lnb[c + 1]);
            uint32_t kb = ((uint32_t)(cl * 2)) ^ rswz;
            {
                float t0 = fmaxf((acc[mi][ni][0] - mu[mi][0]) * rsd[mi][0] * g0 + B0, 0.f);
                float t1 = fmaxf((acc[mi][ni][1] - mu[mi][0]) * rsd[mi][0] * g1 + B1, 0.f);
                *(uint32_t*)(a2 + (uint32_t)warp_n * TILE_B + (uint32_t)rl * 128 + kb) = pkh(t0, t1);
            }
            {
                float t0 = fmaxf((acc[mi][ni][2] - mu[mi][1]) * rsd[mi][1] * g0 + B0, 0.f);
                float t1 = fmaxf((acc[mi][ni][3] - mu[mi][1]) * rsd[mi][1] * g1 + B1, 0.f);
                *(uint32_t*)(a2 + (uint32_t)warp_n * TILE_B + (uint32_t)rh * 128 + kb) = pkh(t0, t1);
            }
        }
    }
}

// stage acc (bias already included) into fp32 smem tile [64][SP]
__device__ __forceinline__ void stage_acc(float (*acc)[8][4], float* stg,
                                          int lane, int m_base, int n_base)
{
    #pragma unroll
    for (int mi = 0; mi < 2; mi++) {
        int rl = m_base + mi * 16 + (lane >> 2);
        int rh = rl + 8;
        #pragma unroll
        for (int ni = 0; ni < 8; ni++) {
            int col = n_base + ni * 8 + 2 * (lane & 3);
            *(float2*)&stg[rl * SP + col] = make_float2(acc[mi][ni][0], acc[mi][ni][1]);
            *(float2*)&stg[rh * SP + col] = make_float2(acc[mi][ni][2], acc[mi][ni][3]);
        }
    }
}

// ---------------- prep: all 4 weights -> transposed fp16 [N][K] ----------------
#define PREP_TOTAL (65536 + 65536 + 81920 + 65536)
__global__ void k_prep_all(const float* __restrict__ wa, const float* __restrict__ wb,
                           const float* __restrict__ wc, const float* __restrict__ wd)
{
    int i = blockIdx.x * 256 + threadIdx.x;
    if (i >= PREP_TOTAL) return;
    const float* w; __half* th; int K, N, j;
    if (i < 65536)       { w = wa; th = g_wa; K = 256; N = 256; j = i; }
    else if (i < 131072) { w = wb; th = g_wb; K = 256; N = 256; j = i - 65536; }
    else if (i < 212992) { w = wc; th = g_wc; K = 320; N = 256; j = i - 131072; }
    else                 { w = wd; th = g_wd; K = 256; N = 256; j = i - 212992; }
    int n = j / K, k = j - n * K;
    th[j] = __float2half(__ldg(&w[(size_t)k * N + n]));
}

// ---------------- smem offsets ----------------
// K1: A 4 tiles (32K) @0, B ring 2x32K @32768, ps 2K @98304, ids @100352
#define K1_A   0
#define K1_B0  32768
#define K1_PS  98304
#define K1_EID 100352
#define K1_NID 100608
#define K1_SMEM 100864

// K2: A 5 tiles (40K) @0, B ring 2x32K @40960, ps 2K @106496, ids @108544
#define K2_A   0
#define K2_B0  40960
#define K2_PS  106496
#define K2_EID 108544
#define K2_NID 108800
#define K2_RC  109056
#define K2_SMEM 109312

// =====================================================================
// Kernel 1: node -> hyperedge  (also zeroes g_acc/g_deg slices for k_e2n)
// =====================================================================
__global__ __launch_bounds__(256, 2)
void k_n2e(const float* __restrict__ x,
           const int*   __restrict__ node_ids,
           const int*   __restrict__ he_ids,
           const float* __restrict__ b1,
           const float* __restrict__ lng, const float* __restrict__ lnb,
           const float* __restrict__ b2)
{
    extern __shared__ char sm[];
    const uint32_t smb = s2u(sm);
    const int tid = threadIdx.x, wid = tid >> 5, lane = tid & 31;
    const int warp_m = wid >> 2, warp_n = wid & 3;
    const int m_base = warp_m * 32, n_base = warp_n * 64;
    const int m0 = blockIdx.x * MT;

    int* eid_s = (int*)(sm + K1_EID);
    int* nid_s = (int*)(sm + K1_NID);
    float* ps  = (float*)(sm + K1_PS);
    float* stg = (float*)sm;
    const uint32_t b0 = smb + K1_B0;

    prologue_B(g_wa, DN_, b0, 0, tid);

    // zero this block's slice of g_acc (16 rows) and g_deg — needed only by
    // k_e2n, which starts after this kernel fully retires (kernel boundary).
    // Hidden under the B-prologue / gather latency.
    {
        int zr0 = blockIdx.x * 16;          // 3125 * 16 = 50000 exact
        const float4 z4 = make_float4(0.f, 0.f, 0.f, 0.f);
        #pragma unroll
        for (int it = 0; it < 4; it++) {
            int i = it * 256 + tid;          // 0..1023 = 16 rows x 64 float4
            int r = zr0 + (i >> 6);
            *(float4*)&g_acc[(size_t)r * DN_ + (i & 63) * 4] = z4;
        }
        if (tid < 16) g_deg[zr0 + tid] = 0.f;
    }

    if (tid < MT) {
        int m = m0 + tid;
        eid_s[tid] = he_ids[m];
        nid_s[tid] = node_ids[m];
    }
    __syncthreads();

    // gather x -> single fp16 swizzled A tiles
    for (int i = tid; i < MT * 64; i += 256) {
        int r = i >> 6, c4 = i & 63;
        float4 v = __ldg((const float4*)&x[(size_t)nid_s[r] * DN_ + c4 * 4]);
        u64 h = (u64)pkh(v.x, v.y) | ((u64)pkh(v.z, v.w) << 32);
        int k = c4 * 4, tile = k >> 6, kin = k & 63;
        *(u64*)(sm + K1_A + tile * TILE_B + SW128((uint32_t)(r * 128 + kin * 2))) = h;
    }

    float acc[2][8][4];
    init_bias_reg(acc, b1, lane, n_base);

    // ---- GEMM1: D = X @ W1 (4 chunks, po=0) ----
    run_gemm<4>(g_wa, DN_, smb + K1_A, b0, 0, acc, tid, lane, m_base, n_base);

    // prefetch GEMM2 chunk 0 (po2 = (0+4)&1 = 0) during the LayerNorm
    prologue_B(g_wb, DH_, b0, 0, tid);

    // ---- LN + ReLU -> A2 tiles (alias A1) ----
    ln_apply(acc, lng, lnb, sm + K1_A, ps, lane, m_base, n_base, warp_n);
    init_bias_reg(acc, b2, lane, n_base);

    // ---- GEMM2: D = H @ W2 (4 chunks, po=0) ----
    run_gemm<4>(g_wb, DH_, smb + K1_A, b0, 0, acc, tid, lane, m_base, n_base);

    // ---- epilogue: stage to smem, coalesced red4 scatter-add to g_agg ----
    stage_acc(acc, stg, lane, m_base, n_base);
    __syncthreads();
    #pragma unroll 1
    for (int rr = 0; rr < 8; rr++) {
        int row = wid * 8 + rr;
        if (m0 + row < MM) {
            float* dst = &g_agg[(size_t)eid_s[row] * DH_];
            #pragma unroll
            for (int h = 0; h < 2; h++) {
                int col = h * 128 + lane * 4;
                float4 v = *(float4*)&stg[row * SP + col];
                red4(&dst[col], v.x, v.y, v.z, v.w);
            }
        }
    }
}

// =====================================================================
// Kernel 2: hyperedge -> node, GEMM1 K = 320
// =====================================================================
__global__ __launch_bounds__(256, 2)
void k_e2n(const int*   __restrict__ node_ids,
           const int*   __restrict__ he_ids,
           const float* __restrict__ he_attr,
           const float* __restrict__ he_count,
           const float* __restrict__ b1,
           const float* __restrict__ lng, const float* __restrict__ lnb,
           const float* __restrict__ b2)
{
    extern __shared__ char sm[];
    const uint32_t smb = s2u(sm);
    const int tid = threadIdx.x, wid = tid >> 5, lane = tid & 31;
    const int warp_m = wid >> 2, warp_n = wid & 3;
    const int m_base = warp_m * 32, n_base = warp_n * 64;
    const int m0 = blockIdx.x * MT;

    int* eid_s = (int*)(sm + K2_EID);
    int* nid_s = (int*)(sm + K2_NID);
    float* rc_s = (float*)(sm + K2_RC);
    float* ps  = (float*)(sm + K2_PS);
    float* stg = (float*)sm;
    const uint32_t b0 = smb + K2_B0;

    prologue_B(g_wc, DIN_, b0, 0, tid);

    if (tid < MT) {
        int m = m0 + tid;
        int e = he_ids[m];
        eid_s[tid] = e;
        nid_s[tid] = node_ids[m];
        rc_s[tid]  = 1.f / (__ldg(&he_count[e]) + 1e-6f);
    }
    __syncthreads();

    // gather [he_attr | agg/cnt] -> single fp16 swizzled A tiles (5 tiles)
    for (int i = tid; i < MT * 16; i += 256) {            // attr: k 0..63 (tile 0)
        int r = i >> 4, q = i & 15;
        float4 v = __ldg((const float4*)&he_attr[(size_t)eid_s[r] * DHA_ + q * 4]);
        u64 h = (u64)pkh(v.x, v.y) | ((u64)pkh(v.z, v.w) << 32);
        *(u64*)(sm + K2_A + SW128((uint32_t)(r * 128 + q * 8))) = h;
    }
    for (int i = tid; i < MT * 64; i += 256) {            // agg: k 64..319 (tiles 1-4)
        int r = i >> 6, c4 = i & 63;
        float rc = rc_s[r];
        float4 v = *(const float4*)&g_agg[(size_t)eid_s[r] * DH_ + c4 * 4];
        v.x *= rc; v.y *= rc; v.z *= rc; v.w *= rc;
        u64 h = (u64)pkh(v.x, v.y) | ((u64)pkh(v.z, v.w) << 32);
        int k = 64 + c4 * 4, tile = k >> 6, kin = k & 63;
        *(u64*)(sm + K2_A + tile * TILE_B + SW128((uint32_t)(r * 128 + kin * 2))) = h;
    }

    float acc[2][8][4];
    init_bias_reg(acc, b1, lane, n_base);

    // ---- GEMM1: D = [attr|agg] @ W1, K = 320 (5 chunks, po=0) ----
    run_gemm<5>(g_wc, DIN_, smb + K2_A, b0, 0, acc, tid, lane, m_base, n_base);

    // prefetch GEMM2 chunk 0 (po2 = (0+5)&1 = 1) during the LayerNorm
    prologue_B(g_wd, DH_, b0, 1, tid);

    // ---- LN + ReLU -> A2 tiles (alias A1 tiles 0-3) ----
    ln_apply(acc, lng, lnb, sm + K2_A, ps, lane, m_base, n_base, warp_n);
    init_bias_reg(acc, b2, lane, n_base);

    // ---- GEMM2: D = G @ W2, K = 256 (4 chunks, po=1) ----
    run_gemm<4>(g_wd, DH_, smb + K2_A, b0, 1, acc, tid, lane, m_base, n_base);

    // ---- epilogue: stage, coalesced relu+red4 scatter-add to g_acc + degree ----
    stage_acc(acc, stg, lane, m_base, n_base);
    __syncthreads();
    #pragma unroll 1
    for (int rr = 0; rr < 8; rr++) {
        int row = wid * 8 + rr;
        if (m0 + row < MM) {
            int n = nid_s[row];
            float* dst = &g_acc[(size_t)n * DN_];
            #pragma unroll
            for (int h = 0; h < 2; h++) {
                int col = h * 128 + lane * 4;
                float4 v = *(float4*)&stg[row * SP + col];
                red4(&dst[col], fmaxf(v.x, 0.f), fmaxf(v.y, 0.f),
                                fmaxf(v.z, 0.f), fmaxf(v.w, 0.f));
            }
            if (lane == 0)
                asm volatile("red.global.add.f32 [%0], %1;" :: "l"(&g_deg[n]), "f"(1.f) : "memory");
        }
    }
}

// =====================================================================
// Kernel 3: out = x + LN(g_acc / (deg + eps)).  Warp per node row.
// =====================================================================
__global__ __launch_bounds__(256, 4)
void k_final(const float* __restrict__ x,
             const float* __restrict__ lng, const float* __restrict__ lnb,
             float* __restrict__ out)
{
    const int lane = threadIdx.x & 31;
    const int n = blockIdx.x * 8 + (threadIdx.x >> 5);
    if (n >= NN) return;

    float rd = 1.f / (g_deg[n] + 1e-6f);
    float v[8], s = 0.f, sq = 0.f;
    #pragma unroll
    for (int j = 0; j < 8; j++) {
        v[j] = g_acc[(size_t)n * DN_ + lane + j * 32] * rd;
        s += v[j]; sq += v[j] * v[j];
    }
    #pragma unroll
    for (int o = 16; o; o >>= 1) {
        s  += __shfl_xor_sync(0xffffffffu, s, o);
        sq += __shfl_xor_sync(0xffffffffu, sq, o);
    }
    float mu = s * (1.f / DN_);
    float var = sq * (1.f / DN_) - mu * mu;
    float rs = rsqrtf(var + 1e-5f);
    #pragma unroll
    for (int j = 0; j < 8; j++) {
        int c = lane + j * 32;
        float t = (v[j] - mu) * rs * __ldg(&lng[c]) + __ldg(&lnb[c]);
        out[(size_t)n * DN_ + c] = __ldg(&x[(size_t)n * DN_ + c]) + t;
    }
}

// =====================================================================
// launcher
// =====================================================================
extern "C" void kernel_launch(void* const* d_in, const int* in_sizes, int n_in,
                              void* d_out, int out_size)
{
    const float* x        = (const float*)d_in[0];
    const int*   node_ids = (const int*)  d_in[1];
    const int*   he_ids   = (const int*)  d_in[2];
    const float* he_attr  = (const float*)d_in[3];
    const float* he_count = (const float*)d_in[4];
    const float* n2e_w1   = (const float*)d_in[5];
    const float* n2e_b1   = (const float*)d_in[6];
    const float* n2e_lng  = (const float*)d_in[7];
    const float* n2e_lnb  = (const float*)d_in[8];
    const float* n2e_w2   = (const float*)d_in[9];
    const float* n2e_b2   = (const float*)d_in[10];
    const float* e2n_w1   = (const float*)d_in[11];
    const float* e2n_b1   = (const float*)d_in[12];
    const float* e2n_lng  = (const float*)d_in[13];
    const float* e2n_lnb  = (const float*)d_in[14];
    const float* e2n_w2   = (const float*)d_in[15];
    const float* e2n_b2   = (const float*)d_in[16];
    const float* ln_g     = (const float*)d_in[17];
    const float* ln_b     = (const float*)d_in[18];
    float* out = (float*)d_out;

    // only g_agg needs a serial zero (consumed by k_n2e's own epilogue);
    // g_acc/g_deg are zeroed inside k_n2e (consumed only by k_e2n).
    void* p_agg;
    cudaGetSymbolAddress(&p_agg, g_agg);
    cudaMemsetAsync(p_agg, 0, sizeof(float) * (size_t)EE * DH_);

    k_prep_all<<<(PREP_TOTAL + 255) / 256, 256>>>(n2e_w1, n2e_w2, e2n_w1, e2n_w2);

    cudaFuncSetAttribute(k_n2e, cudaFuncAttributeMaxDynamicSharedMemorySize, K1_SMEM);
    cudaFuncSetAttribute(k_e2n, cudaFuncAttributeMaxDynamicSharedMemorySize, K2_SMEM);

    k_n2e<<<GRID1, 256, K1_SMEM>>>(x, node_ids, he_ids,
                                   n2e_b1, n2e_lng, n2e_lnb, n2e_b2);
    k_e2n<<<GRID1, 256, K2_SMEM>>>(node_ids, he_ids, he_attr, he_count,
                                   e2n_b1, e2n_lng, e2n_lnb, e2n_b2);
    k_final<<<(NN + 7) / 8, 256>>>(x, ln_g, ln_b, out);
}

// round 17
// speedup vs baseline: 3.0939x; 1.0324x over previous
#include <cuda_runtime.h>
#include <cuda_fp16.h>
#include <cstdint>

// ---------------- problem constants ----------------
#define NN   50000
#define MM   200000
#define EE   10000
#define DN_  256
#define DHA_ 64
#define DH_  256
#define DIN_ 320

#define MT   64           // rows per block (2 CTAs/SM)
#define KC   64           // K chunk (one SW128 tile)
#define TILE_B (MT * 128) // bytes of one [64][64] fp16 tile = 8192
#define BCH  32768        // bytes of one B chunk [256][64] fp16
#define SP   264          // stage pitch in floats

#define GRID1 (MM / MT)   // 3125 (exact)

typedef unsigned long long u64;

// ---------------- device scratch ----------------
__device__ float g_agg[(size_t)EE * DH_];
__device__ float g_acc[(size_t)NN * DN_];
__device__ float g_deg[NN];

// transposed fp16 weights: [N][K]
__device__ __half g_wa[DN_ * DH_];    // n2e_w1^T [256][256]
__device__ __half g_wb[DH_ * DH_];    // n2e_w2^T [256][256]
__device__ __half g_wc[DH_ * DIN_];   // e2n_w1^T [256][320]
__device__ __half g_wd[DN_ * DH_];    // e2n_w2^T [256][256]

// ---------------- helpers ----------------
__device__ __forceinline__ uint32_t s2u(const void* p) {
    uint32_t a;
    asm("{ .reg .u64 t; cvta.to.shared.u64 t, %1; cvt.u32.u64 %0, t; }" : "=r"(a) : "l"(p));
    return a;
}
#define SW128(x) ((x) ^ ((((x) >> 3) & 0x70)))

__device__ __forceinline__ void ldsm4(uint32_t* r, uint32_t a) {
    asm volatile("ldmatrix.sync.aligned.m8n8.x4.shared.b16 {%0,%1,%2,%3}, [%4];"
        : "=r"(r[0]), "=r"(r[1]), "=r"(r[2]), "=r"(r[3]) : "r"(a));
}
__device__ __forceinline__ void mma16816h(float* d, const uint32_t* a, const uint32_t* b) {
    asm volatile("mma.sync.aligned.m16n8k16.row.col.f32.f16.f16.f32 "
        "{%0,%1,%2,%3}, {%4,%5,%6,%7}, {%8,%9}, {%0,%1,%2,%3};"
        : "+f"(d[0]), "+f"(d[1]), "+f"(d[2]), "+f"(d[3])
        : "r"(a[0]), "r"(a[1]), "r"(a[2]), "r"(a[3]), "r"(b[0]), "r"(b[1]));
}
__device__ __forceinline__ void red4(float* p, float a, float b, float c, float d) {
    asm volatile("red.global.add.v4.f32 [%0], {%1, %2, %3, %4};"
                 :: "l"(p), "f"(a), "f"(b), "f"(c), "f"(d) : "memory");
}
__device__ __forceinline__ void cpa16(uint32_t dst, const void* src) {
    asm volatile("cp.async.cg.shared.global [%0], [%1], 16;" :: "r"(dst), "l"(src) : "memory");
}
#define CP_COMMIT() asm volatile("cp.async.commit_group;" ::: "memory")
#define CP_WAIT0()  asm volatile("cp.async.wait_group 0;" ::: "memory")

// pack 2 floats -> fp16x2 (first arg -> low half / lower address)
__device__ __forceinline__ uint32_t pkh(float lo, float hi) {
    __half2 h = __floats2half2_rn(lo, hi);
    return *reinterpret_cast<uint32_t*>(&h);
}

// ---------------- B chunk load: [256 n][64 k] fp16, coalesced cp.async ----------------
__device__ __forceinline__ void load_B_chunk(const __half* __restrict__ w,
                                             int kc, int kstride,
                                             uint32_t bB, int tid)
{
    #pragma unroll
    for (int it = 0; it < 8; it++) {
        int i = it * 256 + tid;
        int n = i >> 3, q = i & 7;
        size_t src = (size_t)n * kstride + kc * KC + q * 8;
        cpa16(bB + SW128((uint32_t)(n * 128 + q * 16)), w + src);
    }
}

// ---------------- MMA for one k64 chunk (warp tile 32x64) ----------------
__device__ __forceinline__ void gemm_chunk(uint32_t aT, uint32_t bB,
                                           float (*acc)[8][4],
                                           int lane, int m_base, int n_base)
{
    const uint32_t swz  = (uint32_t)(lane & 7) << 4;
    const uint32_t arow = (uint32_t)(m_base + (lane & 15)) * 128;
    const uint32_t aka  = (uint32_t)((lane >> 4) << 3) * 2;
    const uint32_t brow = (uint32_t)(n_base + ((lane >> 4) << 3) + (lane & 7)) * 128;
    const uint32_t bka  = (uint32_t)(((lane >> 3) & 1) << 3) * 2;

    #pragma unroll
    for (int ks = 0; ks < 4; ks++) {
        const uint32_t koff = (uint32_t)ks * 32;
        const uint32_t aoff = arow + ((koff + aka) ^ swz);
        const uint32_t boff = brow + ((koff + bka) ^ swz);
        uint32_t fa[2][4], fb[4][4];
        #pragma unroll
        for (int mi = 0; mi < 2; mi++) ldsm4(fa[mi], aT + aoff + mi * 2048);
        #pragma unroll
        for (int j = 0; j < 4; j++)  ldsm4(fb[j], bB + boff + j * 2048);
        #pragma unroll
        for (int mi = 0; mi < 2; mi++)
            #pragma unroll
            for (int j = 0; j < 4; j++) {
                mma16816h(acc[mi][2 * j],     fa[mi], fb[j]);
                mma16816h(acc[mi][2 * j + 1], fa[mi], fb[j] + 2);
            }
    }
}

// 2-deep-ring pipelined GEMM over C k64 chunks, ONE sync per chunk.
// buf(c) = b0 + ((po + c) & 1) * BCH.  Prologue: chunk 0 committed into buf(po).
// Iter c: wait_group 0 (chunk c's data resident — only its group is pending),
// sync (also proves compute(c-1) done, so buf (c+1)&1 is free), issue load c+1,
// commit, compute chunk c.
template<int C>
__device__ __forceinline__ void run_gemm(const __half* __restrict__ w, int kstride,
                                         uint32_t aBase, uint32_t b0, int po,
                                         float (*acc)[8][4],
                                         int tid, int lane, int m_base, int n_base)
{
    #pragma unroll 1
    for (int c = 0; c < C; c++) {
        CP_WAIT0();
        __syncthreads();
        if (c + 1 < C) {
            load_B_chunk(w, c + 1, kstride, b0 + (uint32_t)((po + c + 1) & 1) * BCH, tid);
            CP_COMMIT();
        }
        gemm_chunk(aBase + c * TILE_B, b0 + (uint32_t)((po + c) & 1) * BCH,
                   acc, lane, m_base, n_base);
    }
}

// prologue: issue chunk 0 into buf(po), one commit group
__device__ __forceinline__ void prologue_B(const __half* __restrict__ w, int kstride,
                                           uint32_t b0, int po, int tid)
{
    load_B_chunk(w, 0, kstride, b0 + (uint32_t)(po & 1) * BCH, tid);
    CP_COMMIT();
}

__device__ __forceinline__ void init_bias_reg(float (*acc)[8][4],
                                              const float* __restrict__ b,
                                              int lane, int n_base)
{
    #pragma unroll
    for (int ni = 0; ni < 8; ni++) {
        int c = n_base + ni * 8 + 2 * (lane & 3);
        float v0 = __ldg(&b[c]), v1 = __ldg(&b[c + 1]);
        #pragma unroll
        for (int mi = 0; mi < 2; mi++) {
            acc[mi][ni][0] = v0; acc[mi][ni][1] = v1;
            acc[mi][ni][2] = v0; acc[mi][ni][3] = v1;
        }
    }
}

// LayerNorm + ReLU on register accumulators -> single fp16 A2 smem tiles.
__device__ __forceinline__ void ln_apply(float (*acc)[8][4],
                                         const float* __restrict__ lng,
                                         const float* __restrict__ lnb,
                                         char* a2, float* ps,
                                         int lane, int m_base, int n_base, int warp_n)
{
    #pragma unroll
    for (int mi = 0; mi < 2; mi++) {
        float sl = 0.f, ql = 0.f, sh = 0.f, qh = 0.f;
        #pragma unroll
        for (int ni = 0; ni < 8; ni++) {
            float a0 = acc[mi][ni][0], a1 = acc[mi][ni][1];
            float a2v = acc[mi][ni][2], a3 = acc[mi][ni][3];
            sl += a0 + a1; ql += a0 * a0 + a1 * a1;
            sh += a2v + a3; qh += a2v * a2v + a3 * a3;
        }
        sl += __shfl_xor_sync(0xffffffffu, sl, 1); sl += __shfl_xor_sync(0xffffffffu, sl, 2);
        ql += __shfl_xor_sync(0xffffffffu, ql, 1); ql += __shfl_xor_sync(0xffffffffu, ql, 2);
        sh += __shfl_xor_sync(0xffffffffu, sh, 1); sh += __shfl_xor_sync(0xffffffffu, sh, 2);
        qh += __shfl_xor_sync(0xffffffffu, qh, 1); qh += __shfl_xor_sync(0xffffffffu, qh, 2);
        if ((lane & 3) == 0) {
            int rl = m_base + mi * 16 + (lane >> 2);
            ps[rl * 4 + warp_n] = sl;        ps[256 + rl * 4 + warp_n] = ql;
            ps[(rl + 8) * 4 + warp_n] = sh;  ps[256 + (rl + 8) * 4 + warp_n] = qh;
        }
    }
    __syncthreads();
    float mu[2][2], rsd[2][2];
    #pragma unroll
    for (int mi = 0; mi < 2; mi++) {
        int rl = m_base + mi * 16 + (lane >> 2);
        #pragma unroll
        for (int h = 0; h < 2; h++) {
            int r = rl + h * 8;
            float s = ps[r * 4] + ps[r * 4 + 1] + ps[r * 4 + 2] + ps[r * 4 + 3];
            float q = ps[256 + r * 4] + ps[256 + r * 4 + 1] + ps[256 + r * 4 + 2] + ps[256 + r * 4 + 3];
            float m = s * (1.f / 256.f);
            float var = q * (1.f / 256.f) - m * m;
            mu[mi][h] = m;
            rsd[mi][h] = rsqrtf(var + 1e-5f);
        }
    }
    __syncthreads();
    #pragma unroll
    for (int mi = 0; mi < 2; mi++) {
        int rl = m_base + mi * 16 + (lane >> 2);
        int rh = rl + 8;
        uint32_t rswz = (uint32_t)(lane >> 2) << 4;
        #pragma unroll
        for (int ni = 0; ni < 8; ni++) {
            int cl = ni * 8 + 2 * (lane & 3);
            int c  = n_base + cl;
            float g0 = __ldg(&lng[c]),  g1 = __ldg(&lng[c + 1]);
            float B0 = __ldg(&lnb[c]),  B1 = __ldg(&lnb[c + 1]);
            uint32_t kb = ((uint32_t)(cl * 2)) ^ rswz;
            {
                float t0 = fmaxf((acc[mi][ni][0] - mu[mi][0]) * rsd[mi][0] * g0 + B0, 0.f);
                float t1 = fmaxf((acc[mi][ni][1] - mu[mi][0]) * rsd[mi][0] * g1 + B1, 0.f);
                *(uint32_t*)(a2 + (uint32_t)warp_n * TILE_B + (uint32_t)rl * 128 + kb) = pkh(t0, t1);
            }
            {
                float t0 = fmaxf((acc[mi][ni][2] - mu[mi][1]) * rsd[mi][1] * g0 + B0, 0.f);
                float t1 = fmaxf((acc[mi][ni][3] - mu[mi][1]) * rsd[mi][1] * g1 + B1, 0.f);
                *(uint32_t*)(a2 + (uint32_t)warp_n * TILE_B + (uint32_t)rh * 128 + kb) = pkh(t0, t1);
            }
        }
    }
}

// stage acc (bias already included) into fp32 smem tile [64][SP]
__device__ __forceinline__ void stage_acc(float (*acc)[8][4], float* stg,
                                          int lane, int m_base, int n_base)
{
    #pragma unroll
    for (int mi = 0; mi < 2; mi++) {
        int rl = m_base + mi * 16 + (lane >> 2);
        int rh = rl + 8;
        #pragma unroll
        for (int ni = 0; ni < 8; ni++) {
            int col = n_base + ni * 8 + 2 * (lane & 3);
            *(float2*)&stg[rl * SP + col] = make_float2(acc[mi][ni][0], acc[mi][ni][1]);
            *(float2*)&stg[rh * SP + col] = make_float2(acc[mi][ni][2], acc[mi][ni][3]);
        }
    }
}

// ---------------- prep: weights -> transposed fp16 [N][K], plus zero g_agg ----------------
// (zeroing folded here removes the serial cudaMemsetAsync; prep fully retires
//  before k_n2e, which is the first consumer of g_agg)
#define PREP_TOTAL (65536 + 65536 + 81920 + 65536)          // 278528
#define ZAGG_ITEMS ((EE * DH_) / 4)                          // 640000 float4
#define PREP_GRID  ((PREP_TOTAL + ZAGG_ITEMS + 255) / 256)   // 3589
__global__ void k_prep_all(const float* __restrict__ wa, const float* __restrict__ wb,
                           const float* __restrict__ wc, const float* __restrict__ wd)
{
    int i = blockIdx.x * 256 + threadIdx.x;
    if (i < PREP_TOTAL) {
        const float* w; __half* th; int K, N, j;
        if (i < 65536)       { w = wa; th = g_wa; K = 256; N = 256; j = i; }
        else if (i < 131072) { w = wb; th = g_wb; K = 256; N = 256; j = i - 65536; }
        else if (i < 212992) { w = wc; th = g_wc; K = 320; N = 256; j = i - 131072; }
        else                 { w = wd; th = g_wd; K = 256; N = 256; j = i - 212992; }
        int n = j / K, k = j - n * K;
        th[j] = __float2half(__ldg(&w[(size_t)k * N + n]));
    } else {
        int z = i - PREP_TOTAL;
        if (z < ZAGG_ITEMS)
            *(float4*)&g_agg[(size_t)z * 4] = make_float4(0.f, 0.f, 0.f, 0.f);
    }
}

// ---------------- smem offsets ----------------
// K1: A 4 tiles (32K) @0, B ring 2x32K @32768, ps 2K @98304, ids @100352
#define K1_A   0
#define K1_B0  32768
#define K1_PS  98304
#define K1_EID 100352
#define K1_NID 100608
#define K1_SMEM 100864

// K2: A 5 tiles (40K) @0, B ring 2x32K @40960, ps 2K @106496, ids @108544
#define K2_A   0
#define K2_B0  40960
#define K2_PS  106496
#define K2_EID 108544
#define K2_NID 108800
#define K2_RC  109056
#define K2_SMEM 109312

// =====================================================================
// Kernel 1: node -> hyperedge  (also zeroes g_acc/g_deg slices for k_e2n)
// =====================================================================
__global__ __launch_bounds__(256, 2)
void k_n2e(const float* __restrict__ x,
           const int*   __restrict__ node_ids,
           const int*   __restrict__ he_ids,
           const float* __restrict__ b1,
           const float* __restrict__ lng, const float* __restrict__ lnb,
           const float* __restrict__ b2)
{
    extern __shared__ char sm[];
    const uint32_t smb = s2u(sm);
    const int tid = threadIdx.x, wid = tid >> 5, lane = tid & 31;
    const int warp_m = wid >> 2, warp_n = wid & 3;
    const int m_base = warp_m * 32, n_base = warp_n * 64;
    const int m0 = blockIdx.x * MT;

    int* eid_s = (int*)(sm + K1_EID);
    int* nid_s = (int*)(sm + K1_NID);
    float* ps  = (float*)(sm + K1_PS);
    float* stg = (float*)sm;
    const uint32_t b0 = smb + K1_B0;

    prologue_B(g_wa, DN_, b0, 0, tid);

    // zero this block's slice of g_acc (16 rows) and g_deg — consumed only by
    // k_e2n (next kernel). Hidden under the B-prologue / gather latency.
    {
        int zr0 = blockIdx.x * 16;          // 3125 * 16 = 50000 exact
        const float4 z4 = make_float4(0.f, 0.f, 0.f, 0.f);
        #pragma unroll
        for (int it = 0; it < 4; it++) {
            int i = it * 256 + tid;          // 0..1023 = 16 rows x 64 float4
            int r = zr0 + (i >> 6);
            *(float4*)&g_acc[(size_t)r * DN_ + (i & 63) * 4] = z4;
        }
        if (tid < 16) g_deg[zr0 + tid] = 0.f;
    }

    if (tid < MT) {
        int m = m0 + tid;
        eid_s[tid] = he_ids[m];
        nid_s[tid] = node_ids[m];
    }
    __syncthreads();

    // gather x -> single fp16 swizzled A tiles
    for (int i = tid; i < MT * 64; i += 256) {
        int r = i >> 6, c4 = i & 63;
        float4 v = __ldg((const float4*)&x[(size_t)nid_s[r] * DN_ + c4 * 4]);
        u64 h = (u64)pkh(v.x, v.y) | ((u64)pkh(v.z, v.w) << 32);
        int k = c4 * 4, tile = k >> 6, kin = k & 63;
        *(u64*)(sm + K1_A + tile * TILE_B + SW128((uint32_t)(r * 128 + kin * 2))) = h;
    }

    float acc[2][8][4];
    init_bias_reg(acc, b1, lane, n_base);

    // ---- GEMM1: D = X @ W1 (4 chunks, po=0) ----
    run_gemm<4>(g_wa, DN_, smb + K1_A, b0, 0, acc, tid, lane, m_base, n_base);

    // prefetch GEMM2 chunk 0 (po2 = (0+4)&1 = 0) during the LayerNorm.
    // buf 0 was last read by GEMM1 chunk 2's compute, which completed before
    // the top-of-iter-3 sync inside run_gemm -> safe to overwrite.
    prologue_B(g_wb, DH_, b0, 0, tid);

    // ---- LN + ReLU -> A2 tiles (alias A1) ----
    ln_apply(acc, lng, lnb, sm + K1_A, ps, lane, m_base, n_base, warp_n);
    init_bias_reg(acc, b2, lane, n_base);

    // ---- GEMM2: D = H @ W2 (4 chunks, po=0) ----
    run_gemm<4>(g_wb, DH_, smb + K1_A, b0, 0, acc, tid, lane, m_base, n_base);

    // ---- epilogue: stage to smem, coalesced red4 scatter-add to g_agg ----
    __syncthreads();   // all warps done with GEMM2 compute before stg aliases A/B
    stage_acc(acc, stg, lane, m_base, n_base);
    __syncthreads();
    #pragma unroll 1
    for (int rr = 0; rr < 8; rr++) {
        int row = wid * 8 + rr;
        if (m0 + row < MM) {
            float* dst = &g_agg[(size_t)eid_s[row] * DH_];
            #pragma unroll
            for (int h = 0; h < 2; h++) {
                int col = h * 128 + lane * 4;
                float4 v = *(float4*)&stg[row * SP + col];
                red4(&dst[col], v.x, v.y, v.z, v.w);
            }
        }
    }
}

// =====================================================================
// Kernel 2: hyperedge -> node, GEMM1 K = 320
// =====================================================================
__global__ __launch_bounds__(256, 2)
void k_e2n(const int*   __restrict__ node_ids,
           const int*   __restrict__ he_ids,
           const float* __restrict__ he_attr,
           const float* __restrict__ he_count,
           const float* __restrict__ b1,
           const float* __restrict__ lng, const float* __restrict__ lnb,
           const float* __restrict__ b2)
{
    extern __shared__ char sm[];
    const uint32_t smb = s2u(sm);
    const int tid = threadIdx.x, wid = tid >> 5, lane = tid & 31;
    const int warp_m = wid >> 2, warp_n = wid & 3;
    const int m_base = warp_m * 32, n_base = warp_n * 64;
    const int m0 = blockIdx.x * MT;

    int* eid_s = (int*)(sm + K2_EID);
    int* nid_s = (int*)(sm + K2_NID);
    float* rc_s = (float*)(sm + K2_RC);
    float* ps  = (float*)(sm + K2_PS);
    float* stg = (float*)sm;
    const uint32_t b0 = smb + K2_B0;

    prologue_B(g_wc, DIN_, b0, 0, tid);

    if (tid < MT) {
        int m = m0 + tid;
        int e = he_ids[m];
        eid_s[tid] = e;
        nid_s[tid] = node_ids[m];
        rc_s[tid]  = 1.f / (__ldg(&he_count[e]) + 1e-6f);
    }
    __syncthreads();

    // gather [he_attr | agg/cnt] -> single fp16 swizzled A tiles (5 tiles)
    for (int i = tid; i < MT * 16; i += 256) {            // attr: k 0..63 (tile 0)
        int r = i >> 4, q = i & 15;
        float4 v = __ldg((const float4*)&he_attr[(size_t)eid_s[r] * DHA_ + q * 4]);
        u64 h = (u64)pkh(v.x, v.y) | ((u64)pkh(v.z, v.w) << 32);
        *(u64*)(sm + K2_A + SW128((uint32_t)(r * 128 + q * 8))) = h;
    }
    for (int i = tid; i < MT * 64; i += 256) {            // agg: k 64..319 (tiles 1-4)
        int r = i >> 6, c4 = i & 63;
        float rc = rc_s[r];
        float4 v = *(const float4*)&g_agg[(size_t)eid_s[r] * DH_ + c4 * 4];
        v.x *= rc; v.y *= rc; v.z *= rc; v.w *= rc;
        u64 h = (u64)pkh(v.x, v.y) | ((u64)pkh(v.z, v.w) << 32);
        int k = 64 + c4 * 4, tile = k >> 6, kin = k & 63;
        *(u64*)(sm + K2_A + tile * TILE_B + SW128((uint32_t)(r * 128 + kin * 2))) = h;
    }

    float acc[2][8][4];
    init_bias_reg(acc, b1, lane, n_base);

    // ---- GEMM1: D = [attr|agg] @ W1, K = 320 (5 chunks, po=0) ----
    run_gemm<5>(g_wc, DIN_, smb + K2_A, b0, 0, acc, tid, lane, m_base, n_base);

    // prefetch GEMM2 chunk 0 (po2 = (0+5)&1 = 1) during the LayerNorm.
    // buf 1 last read by GEMM1 chunk 3, done before iter-4's top sync.
    prologue_B(g_wd, DH_, b0, 1, tid);

    // ---- LN + ReLU -> A2 tiles (alias A1 tiles 0-3) ----
    ln_apply(acc, lng, lnb, sm + K2_A, ps, lane, m_base, n_base, warp_n);
    init_bias_reg(acc, b2, lane, n_base);

    // ---- GEMM2: D = G @ W2, K = 256 (4 chunks, po=1) ----
    run_gemm<4>(g_wd, DH_, smb + K2_A, b0, 1, acc, tid, lane, m_base, n_base);

    // ---- epilogue: stage, coalesced relu+red4 scatter-add to g_acc + degree ----
    __syncthreads();
    stage_acc(acc, stg, lane, m_base, n_base);
    __syncthreads();
    #pragma unroll 1
    for (int rr = 0; rr < 8; rr++) {
        int row = wid * 8 + rr;
        if (m0 + row < MM) {
            int n = nid_s[row];
            float* dst = &g_acc[(size_t)n * DN_];
            #pragma unroll
            for (int h = 0; h < 2; h++) {
                int col = h * 128 + lane * 4;
                float4 v = *(float4*)&stg[row * SP + col];
                red4(&dst[col], fmaxf(v.x, 0.f), fmaxf(v.y, 0.f),
                                fmaxf(v.z, 0.f), fmaxf(v.w, 0.f));
            }
            if (lane == 0)
                asm volatile("red.global.add.f32 [%0], %1;" :: "l"(&g_deg[n]), "f"(1.f) : "memory");
        }
    }
}

// =====================================================================
// Kernel 3: out = x + LN(g_acc / (deg + eps)).  Warp per node row.
// =====================================================================
__global__ __launch_bounds__(256, 4)
void k_final(const float* __restrict__ x,
             const float* __restrict__ lng, const float* __restrict__ lnb,
             float* __restrict__ out)
{
    const int lane = threadIdx.x & 31;
    const int n = blockIdx.x * 8 + (threadIdx.x >> 5);
    if (n >= NN) return;

    float rd = 1.f / (g_deg[n] + 1e-6f);
    float v[8], s = 0.f, sq = 0.f;
    #pragma unroll
    for (int j = 0; j < 8; j++) {
        v[j] = g_acc[(size_t)n * DN_ + lane + j * 32] * rd;
        s += v[j]; sq += v[j] * v[j];
    }
    #pragma unroll
    for (int o = 16; o; o >>= 1) {
        s  += __shfl_xor_sync(0xffffffffu, s, o);
        sq += __shfl_xor_sync(0xffffffffu, sq, o);
    }
    float mu = s * (1.f / DN_);
    float var = sq * (1.f / DN_) - mu * mu;
    float rs = rsqrtf(var + 1e-5f);
    #pragma unroll
    for (int j = 0; j < 8; j++) {
        int c = lane + j * 32;
        float t = (v[j] - mu) * rs * __ldg(&lng[c]) + __ldg(&lnb[c]);
        out[(size_t)n * DN_ + c] = __ldg(&x[(size_t)n * DN_ + c]) + t;
    }
}

// =====================================================================
// launcher  (4 launches per replay: prep, n2e, e2n, final — no memset)
// =====================================================================
extern "C" void kernel_launch(void* const* d_in, const int* in_sizes, int n_in,
                              void* d_out, int out_size)
{
    const float* x        = (const float*)d_in[0];
    const int*   node_ids = (const int*)  d_in[1];
    const int*   he_ids   = (const int*)  d_in[2];
    const float* he_attr  = (const float*)d_in[3];
    const float* he_count = (const float*)d_in[4];
    const float* n2e_w1   = (const float*)d_in[5];
    const float* n2e_b1   = (const float*)d_in[6];
    const float* n2e_lng  = (const float*)d_in[7];
    const float* n2e_lnb  = (const float*)d_in[8];
    const float* n2e_w2   = (const float*)d_in[9];
    const float* n2e_b2   = (const float*)d_in[10];
    const float* e2n_w1   = (const float*)d_in[11];
    const float* e2n_b1   = (const float*)d_in[12];
    const float* e2n_lng  = (const float*)d_in[13];
    const float* e2n_lnb  = (const float*)d_in[14];
    const float* e2n_w2   = (const float*)d_in[15];
    const float* e2n_b2   = (const float*)d_in[16];
    const float* ln_g     = (const float*)d_in[17];
    const float* ln_b     = (const float*)d_in[18];
    float* out = (float*)d_out;

    k_prep_all<<<PREP_GRID, 256>>>(n2e_w1, n2e_w2, e2n_w1, e2n_w2);

    cudaFuncSetAttribute(k_n2e, cudaFuncAttributeMaxDynamicSharedMemorySize, K1_SMEM);
    cudaFuncSetAttribute(k_e2n, cudaFuncAttributeMaxDynamicSharedMemorySize, K2_SMEM);

    k_n2e<<<GRID1, 256, K1_SMEM>>>(x, node_ids, he_ids,
                                   n2e_b1, n2e_lng, n2e_lnb, n2e_b2);
    k_e2n<<<GRID1, 256, K2_SMEM>>>(node_ids, he_ids, he_attr, he_count,
                                   e2n_b1, e2n_lng, e2n_lnb, e2n_b2);
    k_final<<<(NN + 7) / 8, 256>>>(x, ln_g, ln_b, out);
}